// round 8
// baseline (speedup 1.0000x reference)
#include <cuda_runtime.h>
#include <stdint.h>
#include <math.h>

// ---------------- problem constants ----------------
#define TT   64            // T
#define NB   256           // N
#define HD   1024          // H
#define ZDIM 1024          // ZS*ZC
#define AD   48            // AS*AC
#define G3   3072          // 3H
#define KAW  1072          // ZDIM + AD
#define NCAT 4096          // G3 + ZDIM (fused step-GEMM width)
#define TNP  (TT*NB)       // 16384
#define NZ   (NB*ZDIM)     // 262144
#define NH   (NB*HD)       // 262144

// output layout (floats): x_logits, r_loc, c_logits, z_prior_logits, z_post_logits
#define OFF_X     ((size_t)0)
#define OFF_R     ((size_t)TT*NB*ZDIM)
#define OFF_C     (OFF_R + (size_t)TT*NB)
#define OFF_PRIOR (OFF_C + (size_t)TT*NB)
#define OFF_POST  (OFF_PRIOR + (size_t)TT*NB*ZDIM)

// ---------------- device scratch (static, no allocs) ----------------
__device__ float g_ee  [(size_t)TNP*ZDIM];  // e@enc_W[H:] + enc_b
__device__ float g_gum [(size_t)TNP*ZDIM];  // gumbel noise
__device__ float g_ai  [(size_t)TNP*G3];    // a@Wih_a^T + bih
__device__ float g_h   [(size_t)TNP*HD];    // all hidden states
__device__ float g_gh  [NB*G3];             // h@Whh^T + bhh (one step)
__device__ float g_Wcat[(size_t)HD*NCAT];   // [Whh^T | enc_W[:H]]
__device__ float g_WihT[(size_t)KAW*G3];    // Wih^T  [k][g]
__device__ int   g_zidx[TT*NB*32];          // sampled categorical indices
__device__ unsigned g_keys[2*TT];           // per-timestep threefry keys

// ---------------- threefry2x32-20 (JAX-compatible) ----------------
__device__ __forceinline__ void tf2x32(unsigned k0, unsigned k1,
                                       unsigned x0, unsigned x1,
                                       unsigned &o0, unsigned &o1) {
    unsigned ks0 = k0, ks1 = k1, ks2 = k0 ^ k1 ^ 0x1BD11BDAu;
    x0 += ks0; x1 += ks1;
    const int RA[4] = {13, 15, 26, 6};
    const int RB[4] = {17, 29, 16, 24};
#pragma unroll
    for (int i = 0; i < 5; i++) {
#pragma unroll
        for (int j = 0; j < 4; j++) {
            int r = (i & 1) ? RB[j] : RA[j];
            x0 += x1;
            x1 = (x1 << r) | (x1 >> (32 - r));
            x1 ^= x0;
        }
        unsigned a = (i == 0) ? ks1 : (i == 1) ? ks2 : (i == 2) ? ks0 : (i == 3) ? ks1 : ks2;
        unsigned b = (i == 0) ? ks2 : (i == 1) ? ks0 : (i == 2) ? ks1 : (i == 3) ? ks2 : ks0;
        x0 += a; x1 += b + (unsigned)(i + 1);
    }
    o0 = x0; o1 = x1;
}

__global__ void keys_k() {
    int t = threadIdx.x;
    if (t < TT) {
        unsigned o0, o1;
        tf2x32(0u, 42u, 0u, (unsigned)t, o0, o1);
        g_keys[2*t]   = o0;
        g_keys[2*t+1] = o1;
    }
}

__global__ void gumbel_k() {
    size_t L = (size_t)blockIdx.x * blockDim.x + threadIdx.x;
    if (L >= (size_t)TNP * ZDIM) return;
    int t = (int)(L >> 18);            // NZ = 2^18
    unsigned i = (unsigned)(L & 0x3FFFFu);
    unsigned o0, o1;
    tf2x32(g_keys[2*t], g_keys[2*t+1], 0u, i, o0, o1);
    unsigned bits = o0 ^ o1;
    float u = __uint_as_float((bits >> 9) | 0x3f800000u) - 1.0f;
    if (!(u > 0.0f)) u = 1.17549435e-38f;
    float l1 = (float)log((double)u);
    float g  = -(float)log((double)(-l1));
    g_gum[L] = g;
}

// ---------------- transpose: out[c*ldout + r] = in[r*C + c] ----------------
__global__ void transpose_k(const float* __restrict__ in, float* __restrict__ outp,
                            int R, int C, int ldout) {
    __shared__ float tile[32][33];
    int c0 = blockIdx.x * 32, r0 = blockIdx.y * 32;
    int x = threadIdx.x, y = threadIdx.y;
#pragma unroll
    for (int dy = 0; dy < 32; dy += 8) {
        int r = r0 + y + dy, c = c0 + x;
        if (r < R && c < C) tile[y + dy][x] = in[(size_t)r * C + c];
    }
    __syncthreads();
#pragma unroll
    for (int dy = 0; dy < 32; dy += 8) {
        int oc = c0 + y + dy, orr = r0 + x;
        if (oc < C && orr < R) outp[(size_t)oc * ldout + orr] = tile[x][y + dy];
    }
}

// copy enc_W[:H] into Wcat columns 3072..4095
__global__ void enccopy_k(const float* __restrict__ encW) {
    int idx = blockIdx.x * blockDim.x + threadIdx.x;   // 1024*1024
    int k = idx >> 10, c = idx & 1023;
    g_Wcat[(size_t)k * NCAT + G3 + c] = encW[(size_t)k * ZDIM + c];
}

// ---------------- generic SGEMM (proven core): C = A@B (+bias) -------------
// single-buffer, scalar smem fill, As padded (+1). k ascending (bit-stable).
template<int BM, int BN, int BK, int TM, int TNt>
__global__ void sgemm_k(const float* __restrict__ A, int lda,
                        const float* __restrict__ B, int ldb,
                        float* __restrict__ C, int ldc, int K,
                        const float* __restrict__ bias) {
    constexpr int TH = (BM / TM) * (BN / TNt);
    __shared__ float As[BK][BM + 1];
    __shared__ float Bs[BK][BN];
    int tid = threadIdx.x;
    int bm = blockIdx.y * BM, bn = blockIdx.x * BN;
    int tx = tid % (BN / TNt), ty = tid / (BN / TNt);
    float acc[TM][TNt];
#pragma unroll
    for (int i = 0; i < TM; i++)
#pragma unroll
        for (int j = 0; j < TNt; j++) acc[i][j] = 0.0f;

    for (int k0 = 0; k0 < K; k0 += BK) {
#pragma unroll
        for (int i = tid; i < BM * BK; i += TH) {
            int r = i / BK, c = i % BK;
            As[c][r] = A[(size_t)(bm + r) * lda + k0 + c];
        }
#pragma unroll
        for (int i = tid; i < BK * BN; i += TH) {
            int r = i / BN, c = i % BN;
            Bs[r][c] = B[(size_t)(k0 + r) * ldb + bn + c];
        }
        __syncthreads();
#pragma unroll
        for (int kk = 0; kk < BK; kk++) {
            float av[TM], bv[TNt];
#pragma unroll
            for (int i = 0; i < TM; i++) av[i] = As[kk][ty * TM + i];
#pragma unroll
            for (int j = 0; j < TNt; j++) bv[j] = Bs[kk][tx * TNt + j];
#pragma unroll
            for (int i = 0; i < TM; i++)
#pragma unroll
                for (int j = 0; j < TNt; j++)
                    acc[i][j] = fmaf(av[i], bv[j], acc[i][j]);
        }
        __syncthreads();
    }
#pragma unroll
    for (int i = 0; i < TM; i++) {
        int row = bm + ty * TM + i;
#pragma unroll
        for (int j = 0; j < TNt; j++) {
            int col = bn + tx * TNt + j;
            float v = acc[i][j];
            if (bias) v += bias[col];
            C[(size_t)row * ldc + col] = v;
        }
    }
}

// ---------------- fused step GEMM: h_t @ [Whh^T | encW] --------------------
// Proven core structure; BM=64,BN=64,BK=32,TM=8,TN=8 -> 64 threads/CTA,
// grid (NCAT/64=64, NB/64=4) = 256 CTAs (all resident, ~2/SM).
// cols 0..3071 -> g_gh (+bhh); cols 3072..4095 -> prior (+ee_t).
__global__ void __launch_bounds__(64) catgemm2_k(
    const float* __restrict__ h,     // [256,1024]
    const float* __restrict__ bhh,
    const float* __restrict__ ee_t,  // [256,1024]
    float* __restrict__ prior)       // [256,1024]
{
    constexpr int BM = 64, BN = 64, BK = 32, TM = 8, TN = 8;
    constexpr int TH = (BM / TM) * (BN / TN);  // 64
    __shared__ float As[BK][BM + 1];
    __shared__ float Bs[BK][BN];
    int tid = threadIdx.x;
    int bm = blockIdx.y * BM, bn = blockIdx.x * BN;
    int tx = tid % (BN / TN), ty = tid / (BN / TN);
    float acc[TM][TN];
#pragma unroll
    for (int i = 0; i < TM; i++)
#pragma unroll
        for (int j = 0; j < TN; j++) acc[i][j] = 0.0f;

    for (int k0 = 0; k0 < HD; k0 += BK) {
#pragma unroll
        for (int i = tid; i < BM * BK; i += TH) {
            int r = i / BK, c = i % BK;
            As[c][r] = h[(size_t)(bm + r) * HD + k0 + c];
        }
#pragma unroll
        for (int i = tid; i < BK * BN; i += TH) {
            int r = i / BN, c = i % BN;
            Bs[r][c] = g_Wcat[(size_t)(k0 + r) * NCAT + bn + c];
        }
        __syncthreads();
#pragma unroll
        for (int kk = 0; kk < BK; kk++) {
            float av[TM], bv[TN];
#pragma unroll
            for (int i = 0; i < TM; i++) av[i] = As[kk][ty * TM + i];
#pragma unroll
            for (int j = 0; j < TN; j++) bv[j] = Bs[kk][tx * TN + j];
#pragma unroll
            for (int i = 0; i < TM; i++)
#pragma unroll
                for (int j = 0; j < TN; j++)
                    acc[i][j] = fmaf(av[i], bv[j], acc[i][j]);
        }
        __syncthreads();
    }

    bool is_gh = (bn < G3);   // BN=64 divides G3 -> uniform per block
#pragma unroll
    for (int i = 0; i < TM; i++) {
        int row = bm + ty * TM + i;
#pragma unroll
        for (int j = 0; j < TN; j++) {
            int col = bn + tx * TN + j;
            float v = acc[i][j];
            if (is_gh) {
                g_gh[(size_t)row * G3 + col] = v + bhh[col];
            } else {
                int c0 = col - G3;
                prior[(size_t)row * ZDIM + c0] = v + ee_t[(size_t)row * ZDIM + c0];
            }
        }
    }
}

// ---------------- fused sample(t) + GRU(t -> t+1), one block per n ---------
// Sample: 8 warps x 4 s-rows each, lane=class, same ballot/ffs semantics.
// GRU: identical scalar math to proven gru_k; h_{t+1} = GRU([z_t,a_t], h_t).
__global__ void samgru_k(int t, const float* __restrict__ zl, int do_gru) {
    int n = blockIdx.x, tid = threadIdx.x;     // 256 threads
    int warp = tid >> 5, lane = tid & 31;
    __shared__ int sidx[32];

#pragma unroll
    for (int q = 0; q < 4; q++) {
        int s = warp * 4 + q;
        size_t off = (size_t)n * ZDIM + s * 32 + lane;
        float v = zl[off] + g_gum[(size_t)t * NZ + off];
        float m = v;
#pragma unroll
        for (int o = 16; o > 0; o >>= 1) m = fmaxf(m, __shfl_xor_sync(0xffffffffu, m, o));
        unsigned b = __ballot_sync(0xffffffffu, v == m);
        if (lane == 0) {
            int idx = __ffs(b) - 1;
            sidx[s] = idx;
            g_zidx[((size_t)t * NB + n) * 32 + s] = idx;
        }
    }
    __syncthreads();
    if (!do_gru) return;

    float acc[12];
    const float* ai = g_ai + ((size_t)t * NB + n) * G3;
#pragma unroll
    for (int c = 0; c < 12; c++) acc[c] = ai[tid + 256 * c];

    for (int s = 0; s < 32; s++) {
        const float* row = g_WihT + (size_t)(s * 32 + sidx[s]) * G3;
#pragma unroll
        for (int c = 0; c < 12; c++) acc[c] += row[tid + 256 * c];
    }

    const float* gh = g_gh + (size_t)n * G3;
    const float* hp = g_h + ((size_t)t * NB + n) * HD;
    float*       ho = g_h + ((size_t)(t + 1) * NB + n) * HD;
#pragma unroll
    for (int c = 0; c < 4; c++) {
        int j = tid + 256 * c;
        float ir = acc[c], iu = acc[c + 4], inn = acc[c + 8];
        float hr = gh[j], hu = gh[HD + j], hn = gh[2 * HD + j];
        float r = 1.0f / (1.0f + expf(-(ir + hr)));
        float u = 1.0f / (1.0f + expf(-(iu + hu)));
        float nn = tanhf(inn + r * hn);
        ho[j] = (1.0f - u) * nn + u * hp[j];
    }
}

// ---------------- decoder z one-hot gather (proven) ------------------------
__global__ void decz_k(const float* __restrict__ decW, float* __restrict__ outx) {
    int tn = blockIdx.x, tid = threadIdx.x;
    __shared__ int sidx[32];
    if (tid < 32) sidx[tid] = g_zidx[(size_t)tn * 32 + tid];
    __syncthreads();
    float* o = outx + (size_t)tn * ZDIM;
    float acc[4];
#pragma unroll
    for (int c = 0; c < 4; c++) acc[c] = o[tid + 256 * c];
    for (int s = 0; s < 32; s++) {
        const float* row = decW + (size_t)(HD + s * 32 + sidx[s]) * ZDIM;
#pragma unroll
        for (int c = 0; c < 4; c++) acc[c] += row[tid + 256 * c];
    }
#pragma unroll
    for (int c = 0; c < 4; c++) o[tid + 256 * c] = acc[c];
}

// ---------------- reward / continue heads ----------------------------------
__global__ void rc_k(const float* __restrict__ rw, const float* __restrict__ cw,
                     const float* __restrict__ cb, float* __restrict__ out) {
    int tn = blockIdx.x, tid = threadIdx.x;
    const float* h = g_h + (size_t)tn * HD;
    float sr = 0.0f, sc = 0.0f;
    for (int j = tid; j < HD; j += 128) {
        float hv = h[j];
        sr += hv * rw[j];
        sc += hv * cw[j];
    }
    __shared__ float br[128], bc[128];
    br[tid] = sr; bc[tid] = sc;
    __syncthreads();
    for (int o = 64; o > 0; o >>= 1) {
        if (tid < o) { br[tid] += br[tid + o]; bc[tid] += bc[tid + o]; }
        __syncthreads();
    }
    if (tid == 0) {
        out[OFF_R + tn] = br[0];
        out[OFF_C + tn] = bc[0] + cb[0];
    }
}

// ---------------- launch ----------------------------------------------------
extern "C" void kernel_launch(void* const* d_in, const int* in_sizes, int n_in,
                              void* d_out, int out_size) {
    const float* x    = (const float*)d_in[0];
    const float* a    = (const float*)d_in[1];
    const float* h0   = (const float*)d_in[2];
    const float* encW = (const float*)d_in[3];
    const float* encb = (const float*)d_in[4];
    const float* Wih  = (const float*)d_in[5];
    const float* Whh  = (const float*)d_in[6];
    const float* bih  = (const float*)d_in[7];
    const float* bhh  = (const float*)d_in[8];
    const float* decW = (const float*)d_in[9];
    const float* decb = (const float*)d_in[10];
    const float* dynW = (const float*)d_in[11];
    const float* dynb = (const float*)d_in[12];
    const float* rewW = (const float*)d_in[13];
    const float* conW = (const float*)d_in[14];
    const float* conb = (const float*)d_in[15];
    float* out = (float*)d_out;

    float *p_ee, *p_ai, *p_h, *p_Wcat, *p_WihT;
    cudaGetSymbolAddress((void**)&p_ee,   g_ee);
    cudaGetSymbolAddress((void**)&p_ai,   g_ai);
    cudaGetSymbolAddress((void**)&p_h,    g_h);
    cudaGetSymbolAddress((void**)&p_Wcat, g_Wcat);
    cudaGetSymbolAddress((void**)&p_WihT, g_WihT);

    // --- parallel precompute ---
    keys_k<<<1, 64>>>();
    gumbel_k<<<(int)(((size_t)TNP * ZDIM + 255) / 256), 256>>>();
    transpose_k<<<dim3(32, 96), dim3(32, 8)>>>(Whh, p_Wcat, G3, HD, NCAT);
    enccopy_k<<<4096, 256>>>(encW);
    transpose_k<<<dim3(34, 96), dim3(32, 8)>>>(Wih, p_WihT, G3, KAW, G3);
    // ee = e @ enc_W[H:] + enc_b   [16384,1024]x[1024,1024]  (K=1024 -> BK=32)
    sgemm_k<128,128,32,8,8><<<dim3(ZDIM / 128, TNP / 128), 256>>>(
        x, ZDIM, encW + (size_t)HD * ZDIM, ZDIM, p_ee, ZDIM, ZDIM, encb);
    // ai = a @ Wih_a^T + bih   [16384,48]x[48,3072]  (K=48 -> BK=16)
    sgemm_k<128,128,16,8,8><<<dim3(G3 / 128, TNP / 128), 256>>>(
        a, AD, p_WihT + (size_t)ZDIM * G3, G3, p_ai, G3, AD, bih);

    // --- sequential rollout ---
    cudaMemcpyAsync(p_h, h0, (size_t)NH * sizeof(float), cudaMemcpyDeviceToDevice, 0);
    for (int t = 0; t < TT; t++) {
        catgemm2_k<<<dim3(NCAT / 64, NB / 64), 64>>>(
            p_h + (size_t)t * NH, bhh, p_ee + (size_t)t * NZ,
            out + OFF_PRIOR + (size_t)t * NZ);
        samgru_k<<<NB, 256>>>(t, out + OFF_PRIOR + (size_t)t * NZ, (t < TT - 1) ? 1 : 0);
    }

    // --- parallel heads ---
    sgemm_k<128,128,32,8,8><<<dim3(ZDIM / 128, TNP / 128), 256>>>(
        p_h, HD, decW, ZDIM, out + OFF_X, ZDIM, HD, decb);
    decz_k<<<TNP, 256>>>(decW, out + OFF_X);
    sgemm_k<128,128,32,8,8><<<dim3(ZDIM / 128, TNP / 128), 256>>>(
        p_h, HD, dynW, ZDIM, out + OFF_POST, ZDIM, HD, dynb);
    rc_k<<<TNP, 128>>>(rewW, conW, conb, out);
}

// round 9
// speedup vs baseline: 1.1191x; 1.1191x over previous
#include <cuda_runtime.h>
#include <stdint.h>
#include <math.h>

// ---------------- problem constants ----------------
#define TT   64            // T
#define NB   256           // N
#define HD   1024          // H
#define ZDIM 1024          // ZS*ZC
#define AD   48            // AS*AC
#define G3   3072          // 3H
#define KAW  1072          // ZDIM + AD
#define NCAT 4096          // G3 + ZDIM (fused step-GEMM width)
#define TNP  (TT*NB)       // 16384
#define NZ   (NB*ZDIM)     // 262144
#define NH   (NB*HD)       // 262144

// output layout (floats): x_logits, r_loc, c_logits, z_prior_logits, z_post_logits
#define OFF_X     ((size_t)0)
#define OFF_R     ((size_t)TT*NB*ZDIM)
#define OFF_C     (OFF_R + (size_t)TT*NB)
#define OFF_PRIOR (OFF_C + (size_t)TT*NB)
#define OFF_POST  (OFF_PRIOR + (size_t)TT*NB*ZDIM)

// ---------------- device scratch (static, no allocs) ----------------
__device__ float g_ee  [(size_t)TNP*ZDIM];  // e@enc_W[H:] + enc_b
__device__ float g_gum [(size_t)TNP*ZDIM];  // gumbel noise
__device__ float g_ai  [(size_t)TNP*G3];    // a@Wih_a^T + bih
__device__ float g_h   [(size_t)TNP*HD];    // all hidden states
__device__ float g_gh  [NB*G3];             // h@Whh^T + bhh (one step)
__device__ float g_Wcat[(size_t)HD*NCAT];   // [Whh^T | enc_W[:H]]
__device__ float g_WihT[(size_t)KAW*G3];    // Wih^T  [k][g]
__device__ int   g_zidx[TT*NB*32];          // sampled categorical indices
__device__ unsigned g_keys[2*TT];           // per-timestep threefry keys

// ---------------- threefry2x32-20 (JAX-compatible) ----------------
__device__ __forceinline__ void tf2x32(unsigned k0, unsigned k1,
                                       unsigned x0, unsigned x1,
                                       unsigned &o0, unsigned &o1) {
    unsigned ks0 = k0, ks1 = k1, ks2 = k0 ^ k1 ^ 0x1BD11BDAu;
    x0 += ks0; x1 += ks1;
    const int RA[4] = {13, 15, 26, 6};
    const int RB[4] = {17, 29, 16, 24};
#pragma unroll
    for (int i = 0; i < 5; i++) {
#pragma unroll
        for (int j = 0; j < 4; j++) {
            int r = (i & 1) ? RB[j] : RA[j];
            x0 += x1;
            x1 = (x1 << r) | (x1 >> (32 - r));
            x1 ^= x0;
        }
        unsigned a = (i == 0) ? ks1 : (i == 1) ? ks2 : (i == 2) ? ks0 : (i == 3) ? ks1 : ks2;
        unsigned b = (i == 0) ? ks2 : (i == 1) ? ks0 : (i == 2) ? ks1 : (i == 3) ? ks2 : ks0;
        x0 += a; x1 += b + (unsigned)(i + 1);
    }
    o0 = x0; o1 = x1;
}

__global__ void keys_k() {
    int t = threadIdx.x;
    if (t < TT) {
        unsigned o0, o1;
        tf2x32(0u, 42u, 0u, (unsigned)t, o0, o1);
        g_keys[2*t]   = o0;
        g_keys[2*t+1] = o1;
    }
}

__global__ void gumbel_k() {
    size_t L = (size_t)blockIdx.x * blockDim.x + threadIdx.x;
    if (L >= (size_t)TNP * ZDIM) return;
    int t = (int)(L >> 18);            // NZ = 2^18
    unsigned i = (unsigned)(L & 0x3FFFFu);
    unsigned o0, o1;
    tf2x32(g_keys[2*t], g_keys[2*t+1], 0u, i, o0, o1);
    unsigned bits = o0 ^ o1;
    float u = __uint_as_float((bits >> 9) | 0x3f800000u) - 1.0f;
    if (!(u > 0.0f)) u = 1.17549435e-38f;
    float l1 = (float)log((double)u);
    float g  = -(float)log((double)(-l1));
    g_gum[L] = g;
}

// ---------------- transpose: out[c*ldout + r] = in[r*C + c] ----------------
__global__ void transpose_k(const float* __restrict__ in, float* __restrict__ outp,
                            int R, int C, int ldout) {
    __shared__ float tile[32][33];
    int c0 = blockIdx.x * 32, r0 = blockIdx.y * 32;
    int x = threadIdx.x, y = threadIdx.y;
#pragma unroll
    for (int dy = 0; dy < 32; dy += 8) {
        int r = r0 + y + dy, c = c0 + x;
        if (r < R && c < C) tile[y + dy][x] = in[(size_t)r * C + c];
    }
    __syncthreads();
#pragma unroll
    for (int dy = 0; dy < 32; dy += 8) {
        int oc = c0 + y + dy, orr = r0 + x;
        if (oc < C && orr < R) outp[(size_t)oc * ldout + orr] = tile[x][y + dy];
    }
}

// copy enc_W[:H] into Wcat columns 3072..4095
__global__ void enccopy_k(const float* __restrict__ encW) {
    int idx = blockIdx.x * blockDim.x + threadIdx.x;   // 1024*1024
    int k = idx >> 10, c = idx & 1023;
    g_Wcat[(size_t)k * NCAT + G3 + c] = encW[(size_t)k * ZDIM + c];
}

// ---------------- generic SGEMM (proven core): C = A@B (+bias) -------------
// single-buffer, scalar smem fill, As padded (+1). k ascending (bit-stable).
template<int BM, int BN, int BK, int TM, int TNt>
__global__ void sgemm_k(const float* __restrict__ A, int lda,
                        const float* __restrict__ B, int ldb,
                        float* __restrict__ C, int ldc, int K,
                        const float* __restrict__ bias) {
    constexpr int TH = (BM / TM) * (BN / TNt);
    __shared__ float As[BK][BM + 1];
    __shared__ float Bs[BK][BN];
    int tid = threadIdx.x;
    int bm = blockIdx.y * BM, bn = blockIdx.x * BN;
    int tx = tid % (BN / TNt), ty = tid / (BN / TNt);
    float acc[TM][TNt];
#pragma unroll
    for (int i = 0; i < TM; i++)
#pragma unroll
        for (int j = 0; j < TNt; j++) acc[i][j] = 0.0f;

    for (int k0 = 0; k0 < K; k0 += BK) {
#pragma unroll
        for (int i = tid; i < BM * BK; i += TH) {
            int r = i / BK, c = i % BK;
            As[c][r] = A[(size_t)(bm + r) * lda + k0 + c];
        }
#pragma unroll
        for (int i = tid; i < BK * BN; i += TH) {
            int r = i / BN, c = i % BN;
            Bs[r][c] = B[(size_t)(k0 + r) * ldb + bn + c];
        }
        __syncthreads();
#pragma unroll
        for (int kk = 0; kk < BK; kk++) {
            float av[TM], bv[TNt];
#pragma unroll
            for (int i = 0; i < TM; i++) av[i] = As[kk][ty * TM + i];
#pragma unroll
            for (int j = 0; j < TNt; j++) bv[j] = Bs[kk][tx * TNt + j];
#pragma unroll
            for (int i = 0; i < TM; i++)
#pragma unroll
                for (int j = 0; j < TNt; j++)
                    acc[i][j] = fmaf(av[i], bv[j], acc[i][j]);
        }
        __syncthreads();
    }
#pragma unroll
    for (int i = 0; i < TM; i++) {
        int row = bm + ty * TM + i;
#pragma unroll
        for (int j = 0; j < TNt; j++) {
            int col = bn + tx * TNt + j;
            float v = acc[i][j];
            if (bias) v += bias[col];
            C[(size_t)row * ldc + col] = v;
        }
    }
}

// ---------------- fused step GEMM: h_t @ [Whh^T | encW] --------------------
// R6-proven config: BM=64,BN=64,BK=16,TM=4,TN=4, 256 threads, grid=256 CTAs.
// cols 0..3071 -> g_gh (+bhh); cols 3072..4095 -> prior (+ee_t).
__global__ void catgemm_k(const float* __restrict__ h,     // [256,1024]
                          const float* __restrict__ bhh,
                          const float* __restrict__ ee_t,  // [256,1024]
                          float* __restrict__ prior)       // [256,1024]
{
    constexpr int BM = 64, BN = 64, BK = 16, TM = 4, TN = 4;
    constexpr int TH = (BM / TM) * (BN / TN);  // 256
    __shared__ float As[BK][BM + 1];
    __shared__ float Bs[BK][BN];
    int tid = threadIdx.x;
    int bm = blockIdx.y * BM, bn = blockIdx.x * BN;
    int tx = tid % (BN / TN), ty = tid / (BN / TN);
    float acc[TM][TN];
#pragma unroll
    for (int i = 0; i < TM; i++)
#pragma unroll
        for (int j = 0; j < TN; j++) acc[i][j] = 0.0f;

    for (int k0 = 0; k0 < HD; k0 += BK) {
#pragma unroll
        for (int i = tid; i < BM * BK; i += TH) {
            int r = i / BK, c = i % BK;
            As[c][r] = h[(size_t)(bm + r) * HD + k0 + c];
        }
#pragma unroll
        for (int i = tid; i < BK * BN; i += TH) {
            int r = i / BN, c = i % BN;
            Bs[r][c] = g_Wcat[(size_t)(k0 + r) * NCAT + bn + c];
        }
        __syncthreads();
#pragma unroll
        for (int kk = 0; kk < BK; kk++) {
            float av[TM], bv[TN];
#pragma unroll
            for (int i = 0; i < TM; i++) av[i] = As[kk][ty * TM + i];
#pragma unroll
            for (int j = 0; j < TN; j++) bv[j] = Bs[kk][tx * TN + j];
#pragma unroll
            for (int i = 0; i < TM; i++)
#pragma unroll
                for (int j = 0; j < TN; j++)
                    acc[i][j] = fmaf(av[i], bv[j], acc[i][j]);
        }
        __syncthreads();
    }

    bool is_gh = (bn < G3);   // BN=64 divides G3 -> uniform per block
#pragma unroll
    for (int i = 0; i < TM; i++) {
        int row = bm + ty * TM + i;
#pragma unroll
        for (int j = 0; j < TN; j++) {
            int col = bn + tx * TN + j;
            float v = acc[i][j];
            if (is_gh) {
                g_gh[(size_t)row * G3 + col] = v + bhh[col];
            } else {
                int c0 = col - G3;
                prior[(size_t)row * ZDIM + c0] = v + ee_t[(size_t)row * ZDIM + c0];
            }
        }
    }
}

// ---------------- fused sample(t) + GRU(t -> t+1), one block per n ---------
// (proven in R8, bit-exact) Sample: 8 warps x 4 s-rows, lane=class.
__global__ void samgru_k(int t, const float* __restrict__ zl, int do_gru) {
    int n = blockIdx.x, tid = threadIdx.x;     // 256 threads
    int warp = tid >> 5, lane = tid & 31;
    __shared__ int sidx[32];

#pragma unroll
    for (int q = 0; q < 4; q++) {
        int s = warp * 4 + q;
        size_t off = (size_t)n * ZDIM + s * 32 + lane;
        float v = zl[off] + g_gum[(size_t)t * NZ + off];
        float m = v;
#pragma unroll
        for (int o = 16; o > 0; o >>= 1) m = fmaxf(m, __shfl_xor_sync(0xffffffffu, m, o));
        unsigned b = __ballot_sync(0xffffffffu, v == m);
        if (lane == 0) {
            int idx = __ffs(b) - 1;
            sidx[s] = idx;
            g_zidx[((size_t)t * NB + n) * 32 + s] = idx;
        }
    }
    __syncthreads();
    if (!do_gru) return;

    float acc[12];
    const float* ai = g_ai + ((size_t)t * NB + n) * G3;
#pragma unroll
    for (int c = 0; c < 12; c++) acc[c] = ai[tid + 256 * c];

    for (int s = 0; s < 32; s++) {
        const float* row = g_WihT + (size_t)(s * 32 + sidx[s]) * G3;
#pragma unroll
        for (int c = 0; c < 12; c++) acc[c] += row[tid + 256 * c];
    }

    const float* gh = g_gh + (size_t)n * G3;
    const float* hp = g_h + ((size_t)t * NB + n) * HD;
    float*       ho = g_h + ((size_t)(t + 1) * NB + n) * HD;
#pragma unroll
    for (int c = 0; c < 4; c++) {
        int j = tid + 256 * c;
        float ir = acc[c], iu = acc[c + 4], inn = acc[c + 8];
        float hr = gh[j], hu = gh[HD + j], hn = gh[2 * HD + j];
        float r = 1.0f / (1.0f + expf(-(ir + hr)));
        float u = 1.0f / (1.0f + expf(-(iu + hu)));
        float nn = tanhf(inn + r * hn);
        ho[j] = (1.0f - u) * nn + u * hp[j];
    }
}

// ---------------- decoder z one-hot gather (proven) ------------------------
__global__ void decz_k(const float* __restrict__ decW, float* __restrict__ outx) {
    int tn = blockIdx.x, tid = threadIdx.x;
    __shared__ int sidx[32];
    if (tid < 32) sidx[tid] = g_zidx[(size_t)tn * 32 + tid];
    __syncthreads();
    float* o = outx + (size_t)tn * ZDIM;
    float acc[4];
#pragma unroll
    for (int c = 0; c < 4; c++) acc[c] = o[tid + 256 * c];
    for (int s = 0; s < 32; s++) {
        const float* row = decW + (size_t)(HD + s * 32 + sidx[s]) * ZDIM;
#pragma unroll
        for (int c = 0; c < 4; c++) acc[c] += row[tid + 256 * c];
    }
#pragma unroll
    for (int c = 0; c < 4; c++) o[tid + 256 * c] = acc[c];
}

// ---------------- reward / continue heads ----------------------------------
__global__ void rc_k(const float* __restrict__ rw, const float* __restrict__ cw,
                     const float* __restrict__ cb, float* __restrict__ out) {
    int tn = blockIdx.x, tid = threadIdx.x;
    const float* h = g_h + (size_t)tn * HD;
    float sr = 0.0f, sc = 0.0f;
    for (int j = tid; j < HD; j += 128) {
        float hv = h[j];
        sr += hv * rw[j];
        sc += hv * cw[j];
    }
    __shared__ float br[128], bc[128];
    br[tid] = sr; bc[tid] = sc;
    __syncthreads();
    for (int o = 64; o > 0; o >>= 1) {
        if (tid < o) { br[tid] += br[tid + o]; bc[tid] += bc[tid + o]; }
        __syncthreads();
    }
    if (tid == 0) {
        out[OFF_R + tn] = br[0];
        out[OFF_C + tn] = bc[0] + cb[0];
    }
}

// ---------------- launch ----------------------------------------------------
extern "C" void kernel_launch(void* const* d_in, const int* in_sizes, int n_in,
                              void* d_out, int out_size) {
    const float* x    = (const float*)d_in[0];
    const float* a    = (const float*)d_in[1];
    const float* h0   = (const float*)d_in[2];
    const float* encW = (const float*)d_in[3];
    const float* encb = (const float*)d_in[4];
    const float* Wih  = (const float*)d_in[5];
    const float* Whh  = (const float*)d_in[6];
    const float* bih  = (const float*)d_in[7];
    const float* bhh  = (const float*)d_in[8];
    const float* decW = (const float*)d_in[9];
    const float* decb = (const float*)d_in[10];
    const float* dynW = (const float*)d_in[11];
    const float* dynb = (const float*)d_in[12];
    const float* rewW = (const float*)d_in[13];
    const float* conW = (const float*)d_in[14];
    const float* conb = (const float*)d_in[15];
    float* out = (float*)d_out;

    float *p_ee, *p_ai, *p_h, *p_Wcat, *p_WihT;
    cudaGetSymbolAddress((void**)&p_ee,   g_ee);
    cudaGetSymbolAddress((void**)&p_ai,   g_ai);
    cudaGetSymbolAddress((void**)&p_h,    g_h);
    cudaGetSymbolAddress((void**)&p_Wcat, g_Wcat);
    cudaGetSymbolAddress((void**)&p_WihT, g_WihT);

    // --- parallel precompute ---
    // Launch order puts sgemm_ee at slot #4 (the profiled launch).
    keys_k<<<1, 64>>>();                                                     // 1
    gumbel_k<<<(int)(((size_t)TNP * ZDIM + 255) / 256), 256>>>();            // 2
    transpose_k<<<dim3(32, 96), dim3(32, 8)>>>(Whh, p_Wcat, G3, HD, NCAT);   // 3
    // ee = e @ enc_W[H:] + enc_b   [16384,1024]x[1024,1024]  (K=1024 -> BK=32)
    sgemm_k<128,128,32,8,8><<<dim3(ZDIM / 128, TNP / 128), 256>>>(           // 4 (profiled)
        x, ZDIM, encW + (size_t)HD * ZDIM, ZDIM, p_ee, ZDIM, ZDIM, encb);
    enccopy_k<<<4096, 256>>>(encW);                                          // 5
    transpose_k<<<dim3(34, 96), dim3(32, 8)>>>(Wih, p_WihT, G3, KAW, G3);    // 6
    // ai = a @ Wih_a^T + bih   [16384,48]x[48,3072]  (K=48 -> BK=16)
    sgemm_k<128,128,16,8,8><<<dim3(G3 / 128, TNP / 128), 256>>>(             // 7
        a, AD, p_WihT + (size_t)ZDIM * G3, G3, p_ai, G3, AD, bih);

    // --- sequential rollout ---
    cudaMemcpyAsync(p_h, h0, (size_t)NH * sizeof(float), cudaMemcpyDeviceToDevice, 0);
    for (int t = 0; t < TT; t++) {
        catgemm_k<<<dim3(NCAT / 64, NB / 64), 256>>>(
            p_h + (size_t)t * NH, bhh, p_ee + (size_t)t * NZ,
            out + OFF_PRIOR + (size_t)t * NZ);
        samgru_k<<<NB, 256>>>(t, out + OFF_PRIOR + (size_t)t * NZ, (t < TT - 1) ? 1 : 0);
    }

    // --- parallel heads ---
    sgemm_k<128,128,32,8,8><<<dim3(ZDIM / 128, TNP / 128), 256>>>(
        p_h, HD, decW, ZDIM, out + OFF_X, ZDIM, HD, decb);
    decz_k<<<TNP, 256>>>(decW, out + OFF_X);
    sgemm_k<128,128,32,8,8><<<dim3(ZDIM / 128, TNP / 128), 256>>>(
        p_h, HD, dynW, ZDIM, out + OFF_POST, ZDIM, HD, dynb);
    rc_k<<<TNP, 128>>>(rewW, conW, conb, out);
}

// round 10
// speedup vs baseline: 1.5950x; 1.4253x over previous
#include <cuda_runtime.h>
#include <stdint.h>
#include <math.h>

// ---------------- problem constants ----------------
#define TT   64            // T
#define NB   256           // N
#define HD   1024          // H
#define ZDIM 1024          // ZS*ZC
#define AD   48            // AS*AC
#define G3   3072          // 3H
#define KAW  1072          // ZDIM + AD
#define NCAT 4096          // G3 + ZDIM (fused step-GEMM width)
#define TNP  (TT*NB)       // 16384
#define NZ   (NB*ZDIM)     // 262144
#define NH   (NB*HD)       // 262144

// output layout (floats): x_logits, r_loc, c_logits, z_prior_logits, z_post_logits
#define OFF_X     ((size_t)0)
#define OFF_R     ((size_t)TT*NB*ZDIM)
#define OFF_C     (OFF_R + (size_t)TT*NB)
#define OFF_PRIOR (OFF_C + (size_t)TT*NB)
#define OFF_POST  (OFF_PRIOR + (size_t)TT*NB*ZDIM)

// ---------------- device scratch (static, no allocs) ----------------
__device__ float g_ee  [(size_t)TNP*ZDIM];  // e@enc_W[H:] + enc_b
__device__ float g_gum [(size_t)TNP*ZDIM];  // gumbel noise
__device__ float g_ai  [(size_t)TNP*G3];    // a@Wih_a^T + bih
__device__ float g_h   [(size_t)TNP*HD];    // all hidden states
__device__ float g_gh  [NB*G3];             // h@Whh^T + bhh (one step)
__device__ float g_Wcat[(size_t)HD*NCAT];   // [Whh^T | enc_W[:H]]
__device__ float g_WihT[(size_t)KAW*G3];    // Wih^T  [k][g]
__device__ int   g_zidx[TT*NB*32];          // sampled categorical indices
__device__ unsigned g_keys[2*TT];           // per-timestep threefry keys

// ---------------- threefry2x32-20 (JAX-compatible) ----------------
__device__ __forceinline__ void tf2x32(unsigned k0, unsigned k1,
                                       unsigned x0, unsigned x1,
                                       unsigned &o0, unsigned &o1) {
    unsigned ks0 = k0, ks1 = k1, ks2 = k0 ^ k1 ^ 0x1BD11BDAu;
    x0 += ks0; x1 += ks1;
    const int RA[4] = {13, 15, 26, 6};
    const int RB[4] = {17, 29, 16, 24};
#pragma unroll
    for (int i = 0; i < 5; i++) {
#pragma unroll
        for (int j = 0; j < 4; j++) {
            int r = (i & 1) ? RB[j] : RA[j];
            x0 += x1;
            x1 = (x1 << r) | (x1 >> (32 - r));
            x1 ^= x0;
        }
        unsigned a = (i == 0) ? ks1 : (i == 1) ? ks2 : (i == 2) ? ks0 : (i == 3) ? ks1 : ks2;
        unsigned b = (i == 0) ? ks2 : (i == 1) ? ks0 : (i == 2) ? ks1 : (i == 3) ? ks2 : ks0;
        x0 += a; x1 += b + (unsigned)(i + 1);
    }
    o0 = x0; o1 = x1;
}

__global__ void keys_k() {
    int t = threadIdx.x;
    if (t < TT) {
        unsigned o0, o1;
        tf2x32(0u, 42u, 0u, (unsigned)t, o0, o1);
        g_keys[2*t]   = o0;
        g_keys[2*t+1] = o1;
    }
}

__global__ void gumbel_k() {
    size_t L = (size_t)blockIdx.x * blockDim.x + threadIdx.x;
    if (L >= (size_t)TNP * ZDIM) return;
    int t = (int)(L >> 18);            // NZ = 2^18
    unsigned i = (unsigned)(L & 0x3FFFFu);
    unsigned o0, o1;
    tf2x32(g_keys[2*t], g_keys[2*t+1], 0u, i, o0, o1);
    unsigned bits = o0 ^ o1;
    float u = __uint_as_float((bits >> 9) | 0x3f800000u) - 1.0f;
    if (!(u > 0.0f)) u = 1.17549435e-38f;
    float l1 = (float)log((double)u);
    float g  = -(float)log((double)(-l1));
    g_gum[L] = g;
}

// ---------------- transpose: out[c*ldout + r] = in[r*C + c] ----------------
__global__ void transpose_k(const float* __restrict__ in, float* __restrict__ outp,
                            int R, int C, int ldout) {
    __shared__ float tile[32][33];
    int c0 = blockIdx.x * 32, r0 = blockIdx.y * 32;
    int x = threadIdx.x, y = threadIdx.y;
#pragma unroll
    for (int dy = 0; dy < 32; dy += 8) {
        int r = r0 + y + dy, c = c0 + x;
        if (r < R && c < C) tile[y + dy][x] = in[(size_t)r * C + c];
    }
    __syncthreads();
#pragma unroll
    for (int dy = 0; dy < 32; dy += 8) {
        int oc = c0 + y + dy, orr = r0 + x;
        if (oc < C && orr < R) outp[(size_t)oc * ldout + orr] = tile[x][y + dy];
    }
}

// copy enc_W[:H] into Wcat columns 3072..4095
__global__ void enccopy_k(const float* __restrict__ encW) {
    int idx = blockIdx.x * blockDim.x + threadIdx.x;   // 1024*1024
    int k = idx >> 10, c = idx & 1023;
    g_Wcat[(size_t)k * NCAT + G3 + c] = encW[(size_t)k * ZDIM + c];
}

// ---------------- generic SGEMM (proven core + occupancy fix) --------------
// single-buffer, scalar smem fill, As padded (+1). k ascending (bit-stable).
// __launch_bounds__(256, 2): R9 ncu showed regs=190 -> 1 CTA/SM, occ 12.4%.
template<int BM, int BN, int BK, int TM, int TNt>
__global__ void __launch_bounds__(256, 2)
sgemm_k(const float* __restrict__ A, int lda,
        const float* __restrict__ B, int ldb,
        float* __restrict__ C, int ldc, int K,
        const float* __restrict__ bias) {
    constexpr int TH = (BM / TM) * (BN / TNt);
    __shared__ float As[BK][BM + 1];
    __shared__ float Bs[BK][BN];
    int tid = threadIdx.x;
    int bm = blockIdx.y * BM, bn = blockIdx.x * BN;
    int tx = tid % (BN / TNt), ty = tid / (BN / TNt);
    float acc[TM][TNt];
#pragma unroll
    for (int i = 0; i < TM; i++)
#pragma unroll
        for (int j = 0; j < TNt; j++) acc[i][j] = 0.0f;

    for (int k0 = 0; k0 < K; k0 += BK) {
#pragma unroll
        for (int i = tid; i < BM * BK; i += TH) {
            int r = i / BK, c = i % BK;
            As[c][r] = A[(size_t)(bm + r) * lda + k0 + c];
        }
#pragma unroll
        for (int i = tid; i < BK * BN; i += TH) {
            int r = i / BN, c = i % BN;
            Bs[r][c] = B[(size_t)(k0 + r) * ldb + bn + c];
        }
        __syncthreads();
#pragma unroll
        for (int kk = 0; kk < BK; kk++) {
            float av[TM], bv[TNt];
#pragma unroll
            for (int i = 0; i < TM; i++) av[i] = As[kk][ty * TM + i];
#pragma unroll
            for (int j = 0; j < TNt; j++) bv[j] = Bs[kk][tx * TNt + j];
#pragma unroll
            for (int i = 0; i < TM; i++)
#pragma unroll
                for (int j = 0; j < TNt; j++)
                    acc[i][j] = fmaf(av[i], bv[j], acc[i][j]);
        }
        __syncthreads();
    }
#pragma unroll
    for (int i = 0; i < TM; i++) {
        int row = bm + ty * TM + i;
#pragma unroll
        for (int j = 0; j < TNt; j++) {
            int col = bn + tx * TNt + j;
            float v = acc[i][j];
            if (bias) v += bias[col];
            C[(size_t)row * ldc + col] = v;
        }
    }
}

// ---------------- fused step GEMM: h_t @ [Whh^T | encW] --------------------
// BM=64,BN=64,BK=16,TM=8,TN=4 -> 128 threads, grid = (64,4) = 256 CTAs.
// 32 FMA per 12 LDS per kk (vs 16:16 in the 4x4 config); launch_bounds(128,4)
// -> 3-4 CTAs/SM = 12-16 warps/SM. Accumulation order per element unchanged.
// cols 0..3071 -> g_gh (+bhh); cols 3072..4095 -> prior (+ee_t).
__global__ void __launch_bounds__(128, 4)
catgemm_k(const float* __restrict__ h,     // [256,1024]
          const float* __restrict__ bhh,
          const float* __restrict__ ee_t,  // [256,1024]
          float* __restrict__ prior)       // [256,1024]
{
    constexpr int BM = 64, BN = 64, BK = 16, TM = 8, TN = 4;
    constexpr int TH = (BM / TM) * (BN / TN);  // 8 * 16 = 128
    __shared__ float As[BK][BM + 1];
    __shared__ float Bs[BK][BN];
    int tid = threadIdx.x;
    int bm = blockIdx.y * BM, bn = blockIdx.x * BN;
    int tx = tid % (BN / TN), ty = tid / (BN / TN);
    float acc[TM][TN];
#pragma unroll
    for (int i = 0; i < TM; i++)
#pragma unroll
        for (int j = 0; j < TN; j++) acc[i][j] = 0.0f;

    for (int k0 = 0; k0 < HD; k0 += BK) {
#pragma unroll
        for (int i = tid; i < BM * BK; i += TH) {
            int r = i / BK, c = i % BK;
            As[c][r] = h[(size_t)(bm + r) * HD + k0 + c];
        }
#pragma unroll
        for (int i = tid; i < BK * BN; i += TH) {
            int r = i / BN, c = i % BN;
            Bs[r][c] = g_Wcat[(size_t)(k0 + r) * NCAT + bn + c];
        }
        __syncthreads();
#pragma unroll
        for (int kk = 0; kk < BK; kk++) {
            float av[TM], bv[TN];
#pragma unroll
            for (int i = 0; i < TM; i++) av[i] = As[kk][ty * TM + i];
#pragma unroll
            for (int j = 0; j < TN; j++) bv[j] = Bs[kk][tx * TN + j];
#pragma unroll
            for (int i = 0; i < TM; i++)
#pragma unroll
                for (int j = 0; j < TN; j++)
                    acc[i][j] = fmaf(av[i], bv[j], acc[i][j]);
        }
        __syncthreads();
    }

    bool is_gh = (bn < G3);   // BN=64 divides G3 -> uniform per block
#pragma unroll
    for (int i = 0; i < TM; i++) {
        int row = bm + ty * TM + i;
#pragma unroll
        for (int j = 0; j < TN; j++) {
            int col = bn + tx * TN + j;
            float v = acc[i][j];
            if (is_gh) {
                g_gh[(size_t)row * G3 + col] = v + bhh[col];
            } else {
                int c0 = col - G3;
                prior[(size_t)row * ZDIM + c0] = v + ee_t[(size_t)row * ZDIM + c0];
            }
        }
    }
}

// ---------------- fused sample(t) + GRU(t -> t+1), one block per n ---------
// (proven, bit-exact) Sample: 8 warps x 4 s-rows, lane=class.
__global__ void samgru_k(int t, const float* __restrict__ zl, int do_gru) {
    int n = blockIdx.x, tid = threadIdx.x;     // 256 threads
    int warp = tid >> 5, lane = tid & 31;
    __shared__ int sidx[32];

#pragma unroll
    for (int q = 0; q < 4; q++) {
        int s = warp * 4 + q;
        size_t off = (size_t)n * ZDIM + s * 32 + lane;
        float v = zl[off] + g_gum[(size_t)t * NZ + off];
        float m = v;
#pragma unroll
        for (int o = 16; o > 0; o >>= 1) m = fmaxf(m, __shfl_xor_sync(0xffffffffu, m, o));
        unsigned b = __ballot_sync(0xffffffffu, v == m);
        if (lane == 0) {
            int idx = __ffs(b) - 1;
            sidx[s] = idx;
            g_zidx[((size_t)t * NB + n) * 32 + s] = idx;
        }
    }
    __syncthreads();
    if (!do_gru) return;

    float acc[12];
    const float* ai = g_ai + ((size_t)t * NB + n) * G3;
#pragma unroll
    for (int c = 0; c < 12; c++) acc[c] = ai[tid + 256 * c];

    for (int s = 0; s < 32; s++) {
        const float* row = g_WihT + (size_t)(s * 32 + sidx[s]) * G3;
#pragma unroll
        for (int c = 0; c < 12; c++) acc[c] += row[tid + 256 * c];
    }

    const float* gh = g_gh + (size_t)n * G3;
    const float* hp = g_h + ((size_t)t * NB + n) * HD;
    float*       ho = g_h + ((size_t)(t + 1) * NB + n) * HD;
#pragma unroll
    for (int c = 0; c < 4; c++) {
        int j = tid + 256 * c;
        float ir = acc[c], iu = acc[c + 4], inn = acc[c + 8];
        float hr = gh[j], hu = gh[HD + j], hn = gh[2 * HD + j];
        float r = 1.0f / (1.0f + expf(-(ir + hr)));
        float u = 1.0f / (1.0f + expf(-(iu + hu)));
        float nn = tanhf(inn + r * hn);
        ho[j] = (1.0f - u) * nn + u * hp[j];
    }
}

// ---------------- decoder z one-hot gather (proven) ------------------------
__global__ void decz_k(const float* __restrict__ decW, float* __restrict__ outx) {
    int tn = blockIdx.x, tid = threadIdx.x;
    __shared__ int sidx[32];
    if (tid < 32) sidx[tid] = g_zidx[(size_t)tn * 32 + tid];
    __syncthreads();
    float* o = outx + (size_t)tn * ZDIM;
    float acc[4];
#pragma unroll
    for (int c = 0; c < 4; c++) acc[c] = o[tid + 256 * c];
    for (int s = 0; s < 32; s++) {
        const float* row = decW + (size_t)(HD + s * 32 + sidx[s]) * ZDIM;
#pragma unroll
        for (int c = 0; c < 4; c++) acc[c] += row[tid + 256 * c];
    }
#pragma unroll
    for (int c = 0; c < 4; c++) o[tid + 256 * c] = acc[c];
}

// ---------------- reward / continue heads ----------------------------------
__global__ void rc_k(const float* __restrict__ rw, const float* __restrict__ cw,
                     const float* __restrict__ cb, float* __restrict__ out) {
    int tn = blockIdx.x, tid = threadIdx.x;
    const float* h = g_h + (size_t)tn * HD;
    float sr = 0.0f, sc = 0.0f;
    for (int j = tid; j < HD; j += 128) {
        float hv = h[j];
        sr += hv * rw[j];
        sc += hv * cw[j];
    }
    __shared__ float br[128], bc[128];
    br[tid] = sr; bc[tid] = sc;
    __syncthreads();
    for (int o = 64; o > 0; o >>= 1) {
        if (tid < o) { br[tid] += br[tid + o]; bc[tid] += bc[tid + o]; }
        __syncthreads();
    }
    if (tid == 0) {
        out[OFF_R + tn] = br[0];
        out[OFF_C + tn] = bc[0] + cb[0];
    }
}

// ---------------- launch ----------------------------------------------------
extern "C" void kernel_launch(void* const* d_in, const int* in_sizes, int n_in,
                              void* d_out, int out_size) {
    const float* x    = (const float*)d_in[0];
    const float* a    = (const float*)d_in[1];
    const float* h0   = (const float*)d_in[2];
    const float* encW = (const float*)d_in[3];
    const float* encb = (const float*)d_in[4];
    const float* Wih  = (const float*)d_in[5];
    const float* Whh  = (const float*)d_in[6];
    const float* bih  = (const float*)d_in[7];
    const float* bhh  = (const float*)d_in[8];
    const float* decW = (const float*)d_in[9];
    const float* decb = (const float*)d_in[10];
    const float* dynW = (const float*)d_in[11];
    const float* dynb = (const float*)d_in[12];
    const float* rewW = (const float*)d_in[13];
    const float* conW = (const float*)d_in[14];
    const float* conb = (const float*)d_in[15];
    float* out = (float*)d_out;

    float *p_ee, *p_ai, *p_h, *p_Wcat, *p_WihT;
    cudaGetSymbolAddress((void**)&p_ee,   g_ee);
    cudaGetSymbolAddress((void**)&p_ai,   g_ai);
    cudaGetSymbolAddress((void**)&p_h,    g_h);
    cudaGetSymbolAddress((void**)&p_Wcat, g_Wcat);
    cudaGetSymbolAddress((void**)&p_WihT, g_WihT);

    // --- parallel precompute ---
    // Launch order keeps sgemm_ee at slot #4 (the profiled launch).
    keys_k<<<1, 64>>>();                                                     // 1
    gumbel_k<<<(int)(((size_t)TNP * ZDIM + 255) / 256), 256>>>();            // 2
    transpose_k<<<dim3(32, 96), dim3(32, 8)>>>(Whh, p_Wcat, G3, HD, NCAT);   // 3
    // ee = e @ enc_W[H:] + enc_b   [16384,1024]x[1024,1024]  (K=1024 -> BK=32)
    sgemm_k<128,128,32,8,8><<<dim3(ZDIM / 128, TNP / 128), 256>>>(           // 4 (profiled)
        x, ZDIM, encW + (size_t)HD * ZDIM, ZDIM, p_ee, ZDIM, ZDIM, encb);
    enccopy_k<<<4096, 256>>>(encW);                                          // 5
    transpose_k<<<dim3(34, 96), dim3(32, 8)>>>(Wih, p_WihT, G3, KAW, G3);    // 6
    // ai = a @ Wih_a^T + bih   [16384,48]x[48,3072]  (K=48 -> BK=16)
    sgemm_k<128,128,16,8,8><<<dim3(G3 / 128, TNP / 128), 256>>>(             // 7
        a, AD, p_WihT + (size_t)ZDIM * G3, G3, p_ai, G3, AD, bih);

    // --- sequential rollout ---
    cudaMemcpyAsync(p_h, h0, (size_t)NH * sizeof(float), cudaMemcpyDeviceToDevice, 0);
    for (int t = 0; t < TT; t++) {
        catgemm_k<<<dim3(NCAT / 64, NB / 64), 128>>>(
            p_h + (size_t)t * NH, bhh, p_ee + (size_t)t * NZ,
            out + OFF_PRIOR + (size_t)t * NZ);
        samgru_k<<<NB, 256>>>(t, out + OFF_PRIOR + (size_t)t * NZ, (t < TT - 1) ? 1 : 0);
    }

    // --- parallel heads ---
    sgemm_k<128,128,32,8,8><<<dim3(ZDIM / 128, TNP / 128), 256>>>(
        p_h, HD, decW, ZDIM, out + OFF_X, ZDIM, HD, decb);
    decz_k<<<TNP, 256>>>(decW, out + OFF_X);
    sgemm_k<128,128,32,8,8><<<dim3(ZDIM / 128, TNP / 128), 256>>>(
        p_h, HD, dynW, ZDIM, out + OFF_POST, ZDIM, HD, dynb);
    rc_k<<<TNP, 128>>>(rewW, conW, conb, out);
}

// round 13
// speedup vs baseline: 1.6906x; 1.0599x over previous
#include <cuda_runtime.h>
#include <stdint.h>
#include <math.h>

// ---------------- problem constants ----------------
#define TT   64            // T
#define NB   256           // N
#define HD   1024          // H
#define ZDIM 1024          // ZS*ZC
#define AD   48            // AS*AC
#define G3   3072          // 3H
#define KAW  1072          // ZDIM + AD
#define NCAT 4096          // G3 + ZDIM (fused step-GEMM width)
#define TNP  (TT*NB)       // 16384
#define NZ   (NB*ZDIM)     // 262144
#define NH   (NB*HD)       // 262144

// output layout (floats): x_logits, r_loc, c_logits, z_prior_logits, z_post_logits
#define OFF_X     ((size_t)0)
#define OFF_R     ((size_t)TT*NB*ZDIM)
#define OFF_C     (OFF_R + (size_t)TT*NB)
#define OFF_PRIOR (OFF_C + (size_t)TT*NB)
#define OFF_POST  (OFF_PRIOR + (size_t)TT*NB*ZDIM)

// ---------------- device scratch (static, no allocs) ----------------
__device__ float g_ee  [(size_t)TNP*ZDIM];  // e@enc_W[H:] + enc_b
__device__ float g_gum [(size_t)TNP*ZDIM];  // gumbel noise
__device__ float g_ai  [(size_t)TNP*G3];    // a@Wih_a^T + bih
__device__ float g_h   [(size_t)TNP*HD];    // all hidden states
__device__ float g_gh  [NB*G3];             // h@Whh^T + bhh (one step)
__device__ float g_Wcat[(size_t)HD*NCAT];   // [Whh^T | enc_W[:H]]
__device__ float g_WihT[(size_t)KAW*G3];    // Wih^T  [k][g]
__device__ int   g_zidx[TT*NB*32];          // sampled categorical indices
__device__ unsigned g_keys[2*TT];           // per-timestep threefry keys

// ---------------- threefry2x32-20 (JAX-compatible) ----------------
__device__ __forceinline__ void tf2x32(unsigned k0, unsigned k1,
                                       unsigned x0, unsigned x1,
                                       unsigned &o0, unsigned &o1) {
    unsigned ks0 = k0, ks1 = k1, ks2 = k0 ^ k1 ^ 0x1BD11BDAu;
    x0 += ks0; x1 += ks1;
    const int RA[4] = {13, 15, 26, 6};
    const int RB[4] = {17, 29, 16, 24};
#pragma unroll
    for (int i = 0; i < 5; i++) {
#pragma unroll
        for (int j = 0; j < 4; j++) {
            int r = (i & 1) ? RB[j] : RA[j];
            x0 += x1;
            x1 = (x1 << r) | (x1 >> (32 - r));
            x1 ^= x0;
        }
        unsigned a = (i == 0) ? ks1 : (i == 1) ? ks2 : (i == 2) ? ks0 : (i == 3) ? ks1 : ks2;
        unsigned b = (i == 0) ? ks2 : (i == 1) ? ks0 : (i == 2) ? ks1 : (i == 3) ? ks2 : ks0;
        x0 += a; x1 += b + (unsigned)(i + 1);
    }
    o0 = x0; o1 = x1;
}

__global__ void keys_k() {
    int t = threadIdx.x;
    if (t < TT) {
        unsigned o0, o1;
        tf2x32(0u, 42u, 0u, (unsigned)t, o0, o1);
        g_keys[2*t]   = o0;
        g_keys[2*t+1] = o1;
    }
}

__global__ void gumbel_k() {
    size_t L = (size_t)blockIdx.x * blockDim.x + threadIdx.x;
    if (L >= (size_t)TNP * ZDIM) return;
    int t = (int)(L >> 18);            // NZ = 2^18
    unsigned i = (unsigned)(L & 0x3FFFFu);
    unsigned o0, o1;
    tf2x32(g_keys[2*t], g_keys[2*t+1], 0u, i, o0, o1);
    unsigned bits = o0 ^ o1;
    float u = __uint_as_float((bits >> 9) | 0x3f800000u) - 1.0f;
    if (!(u > 0.0f)) u = 1.17549435e-38f;
    float l1 = (float)log((double)u);
    float g  = -(float)log((double)(-l1));
    g_gum[L] = g;
}

// ---------------- transpose: out[c*ldout + r] = in[r*C + c] ----------------
__global__ void transpose_k(const float* __restrict__ in, float* __restrict__ outp,
                            int R, int C, int ldout) {
    __shared__ float tile[32][33];
    int c0 = blockIdx.x * 32, r0 = blockIdx.y * 32;
    int x = threadIdx.x, y = threadIdx.y;
#pragma unroll
    for (int dy = 0; dy < 32; dy += 8) {
        int r = r0 + y + dy, c = c0 + x;
        if (r < R && c < C) tile[y + dy][x] = in[(size_t)r * C + c];
    }
    __syncthreads();
#pragma unroll
    for (int dy = 0; dy < 32; dy += 8) {
        int oc = c0 + y + dy, orr = r0 + x;
        if (oc < C && orr < R) outp[(size_t)oc * ldout + orr] = tile[x][y + dy];
    }
}

// copy enc_W[:H] into Wcat columns 3072..4095
__global__ void enccopy_k(const float* __restrict__ encW) {
    int idx = blockIdx.x * blockDim.x + threadIdx.x;   // 1024*1024
    int k = idx >> 10, c = idx & 1023;
    g_Wcat[(size_t)k * NCAT + G3 + c] = encW[(size_t)k * ZDIM + c];
}

// ---------------- generic SGEMM: register-staged double buffer -------------
// Same element mapping as proven loader (i = tid + q*TH -> r=i/BK, c=i%BK),
// same k-ascending accumulation per output element (bit-stable canary).
// One __syncthreads per k-tile; LDG for tile kt+1 issues before compute(kt).
// BK=16 keeps double-buffered smem at 32,896B (<48KB static limit).
template<int BM, int BN, int BK, int TM, int TNt>
__global__ void __launch_bounds__(256, 2)
sgemm_k(const float* __restrict__ A, int lda,
        const float* __restrict__ B, int ldb,
        float* __restrict__ C, int ldc, int K,
        const float* __restrict__ bias) {
    constexpr int TH   = (BM / TM) * (BN / TNt);
    constexpr int AREG = BM * BK / TH;
    constexpr int BREG = BK * BN / TH;
    __shared__ float As[2][BK][BM + 1];
    __shared__ float Bs[2][BK][BN];
    int tid = threadIdx.x;
    int bm = blockIdx.y * BM, bn = blockIdx.x * BN;
    int tx = tid % (BN / TNt), ty = tid / (BN / TNt);
    float acc[TM][TNt];
#pragma unroll
    for (int i = 0; i < TM; i++)
#pragma unroll
        for (int j = 0; j < TNt; j++) acc[i][j] = 0.0f;

    float ra[AREG], rb[BREG];

    // prologue: tile 0 -> regs -> smem buf 0
#pragma unroll
    for (int q = 0; q < AREG; q++) {
        int i = tid + q * TH; int r = i / BK, c = i % BK;
        ra[q] = A[(size_t)(bm + r) * lda + c];
    }
#pragma unroll
    for (int q = 0; q < BREG; q++) {
        int i = tid + q * TH; int r = i / BN, c = i % BN;
        rb[q] = B[(size_t)r * ldb + bn + c];
    }
#pragma unroll
    for (int q = 0; q < AREG; q++) {
        int i = tid + q * TH; int r = i / BK, c = i % BK;
        As[0][c][r] = ra[q];
    }
#pragma unroll
    for (int q = 0; q < BREG; q++) {
        int i = tid + q * TH; int r = i / BN, c = i % BN;
        Bs[0][r][c] = rb[q];
    }
    __syncthreads();

    const int NT = K / BK;
    for (int kt = 0; kt < NT; kt++) {
        int cur = kt & 1;
        if (kt + 1 < NT) {
            int k0 = (kt + 1) * BK;
#pragma unroll
            for (int q = 0; q < AREG; q++) {
                int i = tid + q * TH; int r = i / BK, c = i % BK;
                ra[q] = A[(size_t)(bm + r) * lda + k0 + c];
            }
#pragma unroll
            for (int q = 0; q < BREG; q++) {
                int i = tid + q * TH; int r = i / BN, c = i % BN;
                rb[q] = B[(size_t)(k0 + r) * ldb + bn + c];
            }
        }
#pragma unroll
        for (int kk = 0; kk < BK; kk++) {
            float av[TM], bv[TNt];
#pragma unroll
            for (int i = 0; i < TM; i++) av[i] = As[cur][kk][ty * TM + i];
#pragma unroll
            for (int j = 0; j < TNt; j++) bv[j] = Bs[cur][kk][tx * TNt + j];
#pragma unroll
            for (int i = 0; i < TM; i++)
#pragma unroll
                for (int j = 0; j < TNt; j++)
                    acc[i][j] = fmaf(av[i], bv[j], acc[i][j]);
        }
        if (kt + 1 < NT) {
            int nxt = 1 - cur;
#pragma unroll
            for (int q = 0; q < AREG; q++) {
                int i = tid + q * TH; int r = i / BK, c = i % BK;
                As[nxt][c][r] = ra[q];
            }
#pragma unroll
            for (int q = 0; q < BREG; q++) {
                int i = tid + q * TH; int r = i / BN, c = i % BN;
                Bs[nxt][r][c] = rb[q];
            }
        }
        __syncthreads();
    }
#pragma unroll
    for (int i = 0; i < TM; i++) {
        int row = bm + ty * TM + i;
#pragma unroll
        for (int j = 0; j < TNt; j++) {
            int col = bn + tx * TNt + j;
            float v = acc[i][j];
            if (bias) v += bias[col];
            C[(size_t)row * ldc + col] = v;
        }
    }
}

// ---------------- fused step GEMM: h_t @ [Whh^T | encW] --------------------
// Register-staged double buffer; BM=64,BN=64,BK=32,TM=8,TN=4, 128 threads,
// grid = (64,4) = 256 CTAs, 4 CTAs/SM. smem = 33,024B (<48KB).
// cols 0..3071 -> g_gh (+bhh); cols 3072..4095 -> prior (+ee_t).
__global__ void __launch_bounds__(128, 4)
catgemm_k(const float* __restrict__ h,     // [256,1024]
          const float* __restrict__ bhh,
          const float* __restrict__ ee_t,  // [256,1024]
          float* __restrict__ prior)       // [256,1024]
{
    constexpr int BM = 64, BN = 64, BK = 32, TM = 8, TN = 4;
    constexpr int TH   = (BM / TM) * (BN / TN);  // 128
    constexpr int AREG = BM * BK / TH;           // 16
    constexpr int BREG = BK * BN / TH;           // 16
    __shared__ float As[2][BK][BM + 1];
    __shared__ float Bs[2][BK][BN];
    int tid = threadIdx.x;
    int bm = blockIdx.y * BM, bn = blockIdx.x * BN;
    int tx = tid % (BN / TN), ty = tid / (BN / TN);
    float acc[TM][TN];
#pragma unroll
    for (int i = 0; i < TM; i++)
#pragma unroll
        for (int j = 0; j < TN; j++) acc[i][j] = 0.0f;

    float ra[AREG], rb[BREG];

#pragma unroll
    for (int q = 0; q < AREG; q++) {
        int i = tid + q * TH; int r = i / BK, c = i % BK;
        ra[q] = h[(size_t)(bm + r) * HD + c];
    }
#pragma unroll
    for (int q = 0; q < BREG; q++) {
        int i = tid + q * TH; int r = i / BN, c = i % BN;
        rb[q] = g_Wcat[(size_t)r * NCAT + bn + c];
    }
#pragma unroll
    for (int q = 0; q < AREG; q++) {
        int i = tid + q * TH; int r = i / BK, c = i % BK;
        As[0][c][r] = ra[q];
    }
#pragma unroll
    for (int q = 0; q < BREG; q++) {
        int i = tid + q * TH; int r = i / BN, c = i % BN;
        Bs[0][r][c] = rb[q];
    }
    __syncthreads();

    const int NT = HD / BK;
    for (int kt = 0; kt < NT; kt++) {
        int cur = kt & 1;
        if (kt + 1 < NT) {
            int k0 = (kt + 1) * BK;
#pragma unroll
            for (int q = 0; q < AREG; q++) {
                int i = tid + q * TH; int r = i / BK, c = i % BK;
                ra[q] = h[(size_t)(bm + r) * HD + k0 + c];
            }
#pragma unroll
            for (int q = 0; q < BREG; q++) {
                int i = tid + q * TH; int r = i / BN, c = i % BN;
                rb[q] = g_Wcat[(size_t)(k0 + r) * NCAT + bn + c];
            }
        }
#pragma unroll
        for (int kk = 0; kk < BK; kk++) {
            float av[TM], bv[TN];
#pragma unroll
            for (int i = 0; i < TM; i++) av[i] = As[cur][kk][ty * TM + i];
#pragma unroll
            for (int j = 0; j < TN; j++) bv[j] = Bs[cur][kk][tx * TN + j];
#pragma unroll
            for (int i = 0; i < TM; i++)
#pragma unroll
                for (int j = 0; j < TN; j++)
                    acc[i][j] = fmaf(av[i], bv[j], acc[i][j]);
        }
        if (kt + 1 < NT) {
            int nxt = 1 - cur;
#pragma unroll
            for (int q = 0; q < AREG; q++) {
                int i = tid + q * TH; int r = i / BK, c = i % BK;
                As[nxt][c][r] = ra[q];
            }
#pragma unroll
            for (int q = 0; q < BREG; q++) {
                int i = tid + q * TH; int r = i / BN, c = i % BN;
                Bs[nxt][r][c] = rb[q];
            }
        }
        __syncthreads();
    }

    bool is_gh = (bn < G3);   // BN=64 divides G3 -> uniform per block
#pragma unroll
    for (int i = 0; i < TM; i++) {
        int row = bm + ty * TM + i;
#pragma unroll
        for (int j = 0; j < TN; j++) {
            int col = bn + tx * TN + j;
            float v = acc[i][j];
            if (is_gh) {
                g_gh[(size_t)row * G3 + col] = v + bhh[col];
            } else {
                int c0 = col - G3;
                prior[(size_t)row * ZDIM + c0] = v + ee_t[(size_t)row * ZDIM + c0];
            }
        }
    }
}

// ---------------- fused sample(t) + GRU(t -> t+1), one block per n ---------
// (proven, bit-exact) Sample: 8 warps x 4 s-rows, lane=class.
__global__ void samgru_k(int t, const float* __restrict__ zl, int do_gru) {
    int n = blockIdx.x, tid = threadIdx.x;     // 256 threads
    int warp = tid >> 5, lane = tid & 31;
    __shared__ int sidx[32];

#pragma unroll
    for (int q = 0; q < 4; q++) {
        int s = warp * 4 + q;
        size_t off = (size_t)n * ZDIM + s * 32 + lane;
        float v = zl[off] + g_gum[(size_t)t * NZ + off];
        float m = v;
#pragma unroll
        for (int o = 16; o > 0; o >>= 1) m = fmaxf(m, __shfl_xor_sync(0xffffffffu, m, o));
        unsigned b = __ballot_sync(0xffffffffu, v == m);
        if (lane == 0) {
            int idx = __ffs(b) - 1;
            sidx[s] = idx;
            g_zidx[((size_t)t * NB + n) * 32 + s] = idx;
        }
    }
    __syncthreads();
    if (!do_gru) return;

    float acc[12];
    const float* ai = g_ai + ((size_t)t * NB + n) * G3;
#pragma unroll
    for (int c = 0; c < 12; c++) acc[c] = ai[tid + 256 * c];

    for (int s = 0; s < 32; s++) {
        const float* row = g_WihT + (size_t)(s * 32 + sidx[s]) * G3;
#pragma unroll
        for (int c = 0; c < 12; c++) acc[c] += row[tid + 256 * c];
    }

    const float* gh = g_gh + (size_t)n * G3;
    const float* hp = g_h + ((size_t)t * NB + n) * HD;
    float*       ho = g_h + ((size_t)(t + 1) * NB + n) * HD;
#pragma unroll
    for (int c = 0; c < 4; c++) {
        int j = tid + 256 * c;
        float ir = acc[c], iu = acc[c + 4], inn = acc[c + 8];
        float hr = gh[j], hu = gh[HD + j], hn = gh[2 * HD + j];
        float r = 1.0f / (1.0f + expf(-(ir + hr)));
        float u = 1.0f / (1.0f + expf(-(iu + hu)));
        float nn = tanhf(inn + r * hn);
        ho[j] = (1.0f - u) * nn + u * hp[j];
    }
}

// ---------------- decoder z one-hot gather (proven) ------------------------
__global__ void decz_k(const float* __restrict__ decW, float* __restrict__ outx) {
    int tn = blockIdx.x, tid = threadIdx.x;
    __shared__ int sidx[32];
    if (tid < 32) sidx[tid] = g_zidx[(size_t)tn * 32 + tid];
    __syncthreads();
    float* o = outx + (size_t)tn * ZDIM;
    float acc[4];
#pragma unroll
    for (int c = 0; c < 4; c++) acc[c] = o[tid + 256 * c];
    for (int s = 0; s < 32; s++) {
        const float* row = decW + (size_t)(HD + s * 32 + sidx[s]) * ZDIM;
#pragma unroll
        for (int c = 0; c < 4; c++) acc[c] += row[tid + 256 * c];
    }
#pragma unroll
    for (int c = 0; c < 4; c++) o[tid + 256 * c] = acc[c];
}

// ---------------- reward / continue heads ----------------------------------
__global__ void rc_k(const float* __restrict__ rw, const float* __restrict__ cw,
                     const float* __restrict__ cb, float* __restrict__ out) {
    int tn = blockIdx.x, tid = threadIdx.x;
    const float* h = g_h + (size_t)tn * HD;
    float sr = 0.0f, sc = 0.0f;
    for (int j = tid; j < HD; j += 128) {
        float hv = h[j];
        sr += hv * rw[j];
        sc += hv * cw[j];
    }
    __shared__ float br[128], bc[128];
    br[tid] = sr; bc[tid] = sc;
    __syncthreads();
    for (int o = 64; o > 0; o >>= 1) {
        if (tid < o) { br[tid] += br[tid + o]; bc[tid] += bc[tid + o]; }
        __syncthreads();
    }
    if (tid == 0) {
        out[OFF_R + tn] = br[0];
        out[OFF_C + tn] = bc[0] + cb[0];
    }
}

// ---------------- launch ----------------------------------------------------
extern "C" void kernel_launch(void* const* d_in, const int* in_sizes, int n_in,
                              void* d_out, int out_size) {
    const float* x    = (const float*)d_in[0];
    const float* a    = (const float*)d_in[1];
    const float* h0   = (const float*)d_in[2];
    const float* encW = (const float*)d_in[3];
    const float* encb = (const float*)d_in[4];
    const float* Wih  = (const float*)d_in[5];
    const float* Whh  = (const float*)d_in[6];
    const float* bih  = (const float*)d_in[7];
    const float* bhh  = (const float*)d_in[8];
    const float* decW = (const float*)d_in[9];
    const float* decb = (const float*)d_in[10];
    const float* dynW = (const float*)d_in[11];
    const float* dynb = (const float*)d_in[12];
    const float* rewW = (const float*)d_in[13];
    const float* conW = (const float*)d_in[14];
    const float* conb = (const float*)d_in[15];
    float* out = (float*)d_out;

    float *p_ee, *p_ai, *p_h, *p_Wcat, *p_WihT;
    cudaGetSymbolAddress((void**)&p_ee,   g_ee);
    cudaGetSymbolAddress((void**)&p_ai,   g_ai);
    cudaGetSymbolAddress((void**)&p_h,    g_h);
    cudaGetSymbolAddress((void**)&p_Wcat, g_Wcat);
    cudaGetSymbolAddress((void**)&p_WihT, g_WihT);

    // --- parallel precompute ---
    // Launch order keeps sgemm_ee at slot #4 (the profiled launch).
    keys_k<<<1, 64>>>();                                                     // 1
    gumbel_k<<<(int)(((size_t)TNP * ZDIM + 255) / 256), 256>>>();            // 2
    transpose_k<<<dim3(32, 96), dim3(32, 8)>>>(Whh, p_Wcat, G3, HD, NCAT);   // 3
    // ee = e @ enc_W[H:] + enc_b   [16384,1024]x[1024,1024]  (BK=16, dbuf)
    sgemm_k<128,128,16,8,8><<<dim3(ZDIM / 128, TNP / 128), 256>>>(           // 4 (profiled)
        x, ZDIM, encW + (size_t)HD * ZDIM, ZDIM, p_ee, ZDIM, ZDIM, encb);
    enccopy_k<<<4096, 256>>>(encW);                                          // 5
    transpose_k<<<dim3(34, 96), dim3(32, 8)>>>(Wih, p_WihT, G3, KAW, G3);    // 6
    // ai = a @ Wih_a^T + bih   [16384,48]x[48,3072]  (K=48 -> BK=16)
    sgemm_k<128,128,16,8,8><<<dim3(G3 / 128, TNP / 128), 256>>>(             // 7
        a, AD, p_WihT + (size_t)ZDIM * G3, G3, p_ai, G3, AD, bih);

    // --- sequential rollout ---
    cudaMemcpyAsync(p_h, h0, (size_t)NH * sizeof(float), cudaMemcpyDeviceToDevice, 0);
    for (int t = 0; t < TT; t++) {
        catgemm_k<<<dim3(NCAT / 64, NB / 64), 128>>>(
            p_h + (size_t)t * NH, bhh, p_ee + (size_t)t * NZ,
            out + OFF_PRIOR + (size_t)t * NZ);
        samgru_k<<<NB, 256>>>(t, out + OFF_PRIOR + (size_t)t * NZ, (t < TT - 1) ? 1 : 0);
    }

    // --- parallel heads ---
    sgemm_k<128,128,16,8,8><<<dim3(ZDIM / 128, TNP / 128), 256>>>(
        p_h, HD, decW, ZDIM, out + OFF_X, ZDIM, HD, decb);
    decz_k<<<TNP, 256>>>(decW, out + OFF_X);
    sgemm_k<128,128,16,8,8><<<dim3(ZDIM / 128, TNP / 128), 256>>>(
        p_h, HD, dynW, ZDIM, out + OFF_POST, ZDIM, HD, dynb);
    rc_k<<<TNP, 128>>>(rewW, conW, conb, out);
}

// round 14
// speedup vs baseline: 1.6963x; 1.0034x over previous
#include <cuda_runtime.h>
#include <stdint.h>
#include <math.h>

// ---------------- problem constants ----------------
#define TT   64            // T
#define NB   256           // N
#define HD   1024          // H
#define ZDIM 1024          // ZS*ZC
#define AD   48            // AS*AC
#define G3   3072          // 3H
#define KAW  1072          // ZDIM + AD
#define NCAT 4096          // G3 + ZDIM (fused step-GEMM width)
#define TNP  (TT*NB)       // 16384
#define NZ   (NB*ZDIM)     // 262144
#define NH   (NB*HD)       // 262144

// output layout (floats): x_logits, r_loc, c_logits, z_prior_logits, z_post_logits
#define OFF_X     ((size_t)0)
#define OFF_R     ((size_t)TT*NB*ZDIM)
#define OFF_C     (OFF_R + (size_t)TT*NB)
#define OFF_PRIOR (OFF_C + (size_t)TT*NB)
#define OFF_POST  (OFF_PRIOR + (size_t)TT*NB*ZDIM)

// ---------------- device scratch (static, no allocs) ----------------
__device__ float g_ee  [(size_t)TNP*ZDIM];  // e@enc_W[H:] + enc_b
__device__ float g_gum [(size_t)TNP*ZDIM];  // gumbel noise
__device__ float g_ai  [(size_t)TNP*G3];    // a@Wih_a^T + bih
__device__ float g_h   [(size_t)TNP*HD];    // all hidden states
__device__ float g_gh  [NB*G3];             // h@Whh^T + bhh (one step)
__device__ float g_Wcat[(size_t)HD*NCAT];   // [Whh^T | enc_W[:H]]
__device__ float g_WihT[(size_t)KAW*G3];    // Wih^T  [k][g]
__device__ int   g_zidx[TT*NB*32];          // sampled categorical indices
__device__ unsigned g_keys[2*TT];           // per-timestep threefry keys

// ---------------- threefry2x32-20 (JAX-compatible) ----------------
__device__ __forceinline__ void tf2x32(unsigned k0, unsigned k1,
                                       unsigned x0, unsigned x1,
                                       unsigned &o0, unsigned &o1) {
    unsigned ks0 = k0, ks1 = k1, ks2 = k0 ^ k1 ^ 0x1BD11BDAu;
    x0 += ks0; x1 += ks1;
    const int RA[4] = {13, 15, 26, 6};
    const int RB[4] = {17, 29, 16, 24};
#pragma unroll
    for (int i = 0; i < 5; i++) {
#pragma unroll
        for (int j = 0; j < 4; j++) {
            int r = (i & 1) ? RB[j] : RA[j];
            x0 += x1;
            x1 = (x1 << r) | (x1 >> (32 - r));
            x1 ^= x0;
        }
        unsigned a = (i == 0) ? ks1 : (i == 1) ? ks2 : (i == 2) ? ks0 : (i == 3) ? ks1 : ks2;
        unsigned b = (i == 0) ? ks2 : (i == 1) ? ks0 : (i == 2) ? ks1 : (i == 3) ? ks2 : ks0;
        x0 += a; x1 += b + (unsigned)(i + 1);
    }
    o0 = x0; o1 = x1;
}

__global__ void keys_k() {
    int t = threadIdx.x;
    if (t < TT) {
        unsigned o0, o1;
        tf2x32(0u, 42u, 0u, (unsigned)t, o0, o1);
        g_keys[2*t]   = o0;
        g_keys[2*t+1] = o1;
    }
}

__global__ void gumbel_k() {
    size_t L = (size_t)blockIdx.x * blockDim.x + threadIdx.x;
    if (L >= (size_t)TNP * ZDIM) return;
    int t = (int)(L >> 18);            // NZ = 2^18
    unsigned i = (unsigned)(L & 0x3FFFFu);
    unsigned o0, o1;
    tf2x32(g_keys[2*t], g_keys[2*t+1], 0u, i, o0, o1);
    unsigned bits = o0 ^ o1;
    float u = __uint_as_float((bits >> 9) | 0x3f800000u) - 1.0f;
    if (!(u > 0.0f)) u = 1.17549435e-38f;
    float l1 = (float)log((double)u);
    float g  = -(float)log((double)(-l1));
    g_gum[L] = g;
}

// ---------------- transpose: out[c*ldout + r] = in[r*C + c] ----------------
__global__ void transpose_k(const float* __restrict__ in, float* __restrict__ outp,
                            int R, int C, int ldout) {
    __shared__ float tile[32][33];
    int c0 = blockIdx.x * 32, r0 = blockIdx.y * 32;
    int x = threadIdx.x, y = threadIdx.y;
#pragma unroll
    for (int dy = 0; dy < 32; dy += 8) {
        int r = r0 + y + dy, c = c0 + x;
        if (r < R && c < C) tile[y + dy][x] = in[(size_t)r * C + c];
    }
    __syncthreads();
#pragma unroll
    for (int dy = 0; dy < 32; dy += 8) {
        int oc = c0 + y + dy, orr = r0 + x;
        if (oc < C && orr < R) outp[(size_t)oc * ldout + orr] = tile[x][y + dy];
    }
}

// copy enc_W[:H] into Wcat columns 3072..4095
__global__ void enccopy_k(const float* __restrict__ encW) {
    int idx = blockIdx.x * blockDim.x + threadIdx.x;   // 1024*1024
    int k = idx >> 10, c = idx & 1023;
    g_Wcat[(size_t)k * NCAT + G3 + c] = encW[(size_t)k * ZDIM + c];
}

// ---------------- generic SGEMM: register-staged double buffer -------------
// Staging (global->reg->smem) identical to the proven R13 kernel.
// NEW: fragment reads from smem vectorized to LDS.128 (As padded +4 so rows
// stay 16B-aligned). Same elements land in same av/bv slots -> FMA order
// per output element unchanged (bit-stable canary).
template<int BM, int BN, int BK, int TM, int TNt>
__global__ void __launch_bounds__(256, 2)
sgemm_k(const float* __restrict__ A, int lda,
        const float* __restrict__ B, int ldb,
        float* __restrict__ C, int ldc, int K,
        const float* __restrict__ bias) {
    constexpr int TH   = (BM / TM) * (BN / TNt);
    constexpr int AREG = BM * BK / TH;
    constexpr int BREG = BK * BN / TH;
    __shared__ __align__(16) float As[2][BK][BM + 4];
    __shared__ __align__(16) float Bs[2][BK][BN];
    int tid = threadIdx.x;
    int bm = blockIdx.y * BM, bn = blockIdx.x * BN;
    int tx = tid % (BN / TNt), ty = tid / (BN / TNt);
    float acc[TM][TNt];
#pragma unroll
    for (int i = 0; i < TM; i++)
#pragma unroll
        for (int j = 0; j < TNt; j++) acc[i][j] = 0.0f;

    float ra[AREG], rb[BREG];

    // prologue: tile 0 -> regs -> smem buf 0
#pragma unroll
    for (int q = 0; q < AREG; q++) {
        int i = tid + q * TH; int r = i / BK, c = i % BK;
        ra[q] = A[(size_t)(bm + r) * lda + c];
    }
#pragma unroll
    for (int q = 0; q < BREG; q++) {
        int i = tid + q * TH; int r = i / BN, c = i % BN;
        rb[q] = B[(size_t)r * ldb + bn + c];
    }
#pragma unroll
    for (int q = 0; q < AREG; q++) {
        int i = tid + q * TH; int r = i / BK, c = i % BK;
        As[0][c][r] = ra[q];
    }
#pragma unroll
    for (int q = 0; q < BREG; q++) {
        int i = tid + q * TH; int r = i / BN, c = i % BN;
        Bs[0][r][c] = rb[q];
    }
    __syncthreads();

    const int NT = K / BK;
    for (int kt = 0; kt < NT; kt++) {
        int cur = kt & 1;
        if (kt + 1 < NT) {
            int k0 = (kt + 1) * BK;
#pragma unroll
            for (int q = 0; q < AREG; q++) {
                int i = tid + q * TH; int r = i / BK, c = i % BK;
                ra[q] = A[(size_t)(bm + r) * lda + k0 + c];
            }
#pragma unroll
            for (int q = 0; q < BREG; q++) {
                int i = tid + q * TH; int r = i / BN, c = i % BN;
                rb[q] = B[(size_t)(k0 + r) * ldb + bn + c];
            }
        }
#pragma unroll
        for (int kk = 0; kk < BK; kk++) {
            float av[TM], bv[TNt];
            // TM=8 contiguous -> 2x LDS.128 (broadcast across tx)
            float4 a0 = *(const float4*)&As[cur][kk][ty * TM];
            float4 a1 = *(const float4*)&As[cur][kk][ty * TM + 4];
            av[0]=a0.x; av[1]=a0.y; av[2]=a0.z; av[3]=a0.w;
            av[4]=a1.x; av[5]=a1.y; av[6]=a1.z; av[7]=a1.w;
            // TNt=8 contiguous -> 2x LDS.128
            float4 b0 = *(const float4*)&Bs[cur][kk][tx * TNt];
            float4 b1 = *(const float4*)&Bs[cur][kk][tx * TNt + 4];
            bv[0]=b0.x; bv[1]=b0.y; bv[2]=b0.z; bv[3]=b0.w;
            bv[4]=b1.x; bv[5]=b1.y; bv[6]=b1.z; bv[7]=b1.w;
#pragma unroll
            for (int i = 0; i < TM; i++)
#pragma unroll
                for (int j = 0; j < TNt; j++)
                    acc[i][j] = fmaf(av[i], bv[j], acc[i][j]);
        }
        if (kt + 1 < NT) {
            int nxt = 1 - cur;
#pragma unroll
            for (int q = 0; q < AREG; q++) {
                int i = tid + q * TH; int r = i / BK, c = i % BK;
                As[nxt][c][r] = ra[q];
            }
#pragma unroll
            for (int q = 0; q < BREG; q++) {
                int i = tid + q * TH; int r = i / BN, c = i % BN;
                Bs[nxt][r][c] = rb[q];
            }
        }
        __syncthreads();
    }
#pragma unroll
    for (int i = 0; i < TM; i++) {
        int row = bm + ty * TM + i;
#pragma unroll
        for (int j = 0; j < TNt; j++) {
            int col = bn + tx * TNt + j;
            float v = acc[i][j];
            if (bias) v += bias[col];
            C[(size_t)row * ldc + col] = v;
        }
    }
}

// ---------------- fused step GEMM: h_t @ [Whh^T | encW] --------------------
// Register-staged double buffer; BM=64,BN=64,BK=32,TM=8,TN=4, 128 threads,
// grid = (64,4) = 256 CTAs, 4 CTAs/SM. Fragment reads via LDS.128.
// cols 0..3071 -> g_gh (+bhh); cols 3072..4095 -> prior (+ee_t).
__global__ void __launch_bounds__(128, 4)
catgemm_k(const float* __restrict__ h,     // [256,1024]
          const float* __restrict__ bhh,
          const float* __restrict__ ee_t,  // [256,1024]
          float* __restrict__ prior)       // [256,1024]
{
    constexpr int BM = 64, BN = 64, BK = 32, TM = 8, TN = 4;
    constexpr int TH   = (BM / TM) * (BN / TN);  // 128
    constexpr int AREG = BM * BK / TH;           // 16
    constexpr int BREG = BK * BN / TH;           // 16
    __shared__ __align__(16) float As[2][BK][BM + 4];
    __shared__ __align__(16) float Bs[2][BK][BN];
    int tid = threadIdx.x;
    int bm = blockIdx.y * BM, bn = blockIdx.x * BN;
    int tx = tid % (BN / TN), ty = tid / (BN / TN);
    float acc[TM][TN];
#pragma unroll
    for (int i = 0; i < TM; i++)
#pragma unroll
        for (int j = 0; j < TN; j++) acc[i][j] = 0.0f;

    float ra[AREG], rb[BREG];

#pragma unroll
    for (int q = 0; q < AREG; q++) {
        int i = tid + q * TH; int r = i / BK, c = i % BK;
        ra[q] = h[(size_t)(bm + r) * HD + c];
    }
#pragma unroll
    for (int q = 0; q < BREG; q++) {
        int i = tid + q * TH; int r = i / BN, c = i % BN;
        rb[q] = g_Wcat[(size_t)r * NCAT + bn + c];
    }
#pragma unroll
    for (int q = 0; q < AREG; q++) {
        int i = tid + q * TH; int r = i / BK, c = i % BK;
        As[0][c][r] = ra[q];
    }
#pragma unroll
    for (int q = 0; q < BREG; q++) {
        int i = tid + q * TH; int r = i / BN, c = i % BN;
        Bs[0][r][c] = rb[q];
    }
    __syncthreads();

    const int NT = HD / BK;
    for (int kt = 0; kt < NT; kt++) {
        int cur = kt & 1;
        if (kt + 1 < NT) {
            int k0 = (kt + 1) * BK;
#pragma unroll
            for (int q = 0; q < AREG; q++) {
                int i = tid + q * TH; int r = i / BK, c = i % BK;
                ra[q] = h[(size_t)(bm + r) * HD + k0 + c];
            }
#pragma unroll
            for (int q = 0; q < BREG; q++) {
                int i = tid + q * TH; int r = i / BN, c = i % BN;
                rb[q] = g_Wcat[(size_t)(k0 + r) * NCAT + bn + c];
            }
        }
#pragma unroll
        for (int kk = 0; kk < BK; kk++) {
            float av[TM], bv[TN];
            float4 a0 = *(const float4*)&As[cur][kk][ty * TM];
            float4 a1 = *(const float4*)&As[cur][kk][ty * TM + 4];
            av[0]=a0.x; av[1]=a0.y; av[2]=a0.z; av[3]=a0.w;
            av[4]=a1.x; av[5]=a1.y; av[6]=a1.z; av[7]=a1.w;
            float4 b0 = *(const float4*)&Bs[cur][kk][tx * TN];
            bv[0]=b0.x; bv[1]=b0.y; bv[2]=b0.z; bv[3]=b0.w;
#pragma unroll
            for (int i = 0; i < TM; i++)
#pragma unroll
                for (int j = 0; j < TN; j++)
                    acc[i][j] = fmaf(av[i], bv[j], acc[i][j]);
        }
        if (kt + 1 < NT) {
            int nxt = 1 - cur;
#pragma unroll
            for (int q = 0; q < AREG; q++) {
                int i = tid + q * TH; int r = i / BK, c = i % BK;
                As[nxt][c][r] = ra[q];
            }
#pragma unroll
            for (int q = 0; q < BREG; q++) {
                int i = tid + q * TH; int r = i / BN, c = i % BN;
                Bs[nxt][r][c] = rb[q];
            }
        }
        __syncthreads();
    }

    bool is_gh = (bn < G3);   // BN=64 divides G3 -> uniform per block
#pragma unroll
    for (int i = 0; i < TM; i++) {
        int row = bm + ty * TM + i;
#pragma unroll
        for (int j = 0; j < TN; j++) {
            int col = bn + tx * TN + j;
            float v = acc[i][j];
            if (is_gh) {
                g_gh[(size_t)row * G3 + col] = v + bhh[col];
            } else {
                int c0 = col - G3;
                prior[(size_t)row * ZDIM + c0] = v + ee_t[(size_t)row * ZDIM + c0];
            }
        }
    }
}

// ---------------- fused sample(t) + GRU(t -> t+1), one block per n ---------
// (proven, bit-exact) Sample: 8 warps x 4 s-rows, lane=class.
__global__ void samgru_k(int t, const float* __restrict__ zl, int do_gru) {
    int n = blockIdx.x, tid = threadIdx.x;     // 256 threads
    int warp = tid >> 5, lane = tid & 31;
    __shared__ int sidx[32];

#pragma unroll
    for (int q = 0; q < 4; q++) {
        int s = warp * 4 + q;
        size_t off = (size_t)n * ZDIM + s * 32 + lane;
        float v = zl[off] + g_gum[(size_t)t * NZ + off];
        float m = v;
#pragma unroll
        for (int o = 16; o > 0; o >>= 1) m = fmaxf(m, __shfl_xor_sync(0xffffffffu, m, o));
        unsigned b = __ballot_sync(0xffffffffu, v == m);
        if (lane == 0) {
            int idx = __ffs(b) - 1;
            sidx[s] = idx;
            g_zidx[((size_t)t * NB + n) * 32 + s] = idx;
        }
    }
    __syncthreads();
    if (!do_gru) return;

    float acc[12];
    const float* ai = g_ai + ((size_t)t * NB + n) * G3;
#pragma unroll
    for (int c = 0; c < 12; c++) acc[c] = ai[tid + 256 * c];

    for (int s = 0; s < 32; s++) {
        const float* row = g_WihT + (size_t)(s * 32 + sidx[s]) * G3;
#pragma unroll
        for (int c = 0; c < 12; c++) acc[c] += row[tid + 256 * c];
    }

    const float* gh = g_gh + (size_t)n * G3;
    const float* hp = g_h + ((size_t)t * NB + n) * HD;
    float*       ho = g_h + ((size_t)(t + 1) * NB + n) * HD;
#pragma unroll
    for (int c = 0; c < 4; c++) {
        int j = tid + 256 * c;
        float ir = acc[c], iu = acc[c + 4], inn = acc[c + 8];
        float hr = gh[j], hu = gh[HD + j], hn = gh[2 * HD + j];
        float r = 1.0f / (1.0f + expf(-(ir + hr)));
        float u = 1.0f / (1.0f + expf(-(iu + hu)));
        float nn = tanhf(inn + r * hn);
        ho[j] = (1.0f - u) * nn + u * hp[j];
    }
}

// ---------------- decoder z one-hot gather (proven) ------------------------
__global__ void decz_k(const float* __restrict__ decW, float* __restrict__ outx) {
    int tn = blockIdx.x, tid = threadIdx.x;
    __shared__ int sidx[32];
    if (tid < 32) sidx[tid] = g_zidx[(size_t)tn * 32 + tid];
    __syncthreads();
    float* o = outx + (size_t)tn * ZDIM;
    float acc[4];
#pragma unroll
    for (int c = 0; c < 4; c++) acc[c] = o[tid + 256 * c];
    for (int s = 0; s < 32; s++) {
        const float* row = decW + (size_t)(HD + s * 32 + sidx[s]) * ZDIM;
#pragma unroll
        for (int c = 0; c < 4; c++) acc[c] += row[tid + 256 * c];
    }
#pragma unroll
    for (int c = 0; c < 4; c++) o[tid + 256 * c] = acc[c];
}

// ---------------- reward / continue heads ----------------------------------
__global__ void rc_k(const float* __restrict__ rw, const float* __restrict__ cw,
                     const float* __restrict__ cb, float* __restrict__ out) {
    int tn = blockIdx.x, tid = threadIdx.x;
    const float* h = g_h + (size_t)tn * HD;
    float sr = 0.0f, sc = 0.0f;
    for (int j = tid; j < HD; j += 128) {
        float hv = h[j];
        sr += hv * rw[j];
        sc += hv * cw[j];
    }
    __shared__ float br[128], bc[128];
    br[tid] = sr; bc[tid] = sc;
    __syncthreads();
    for (int o = 64; o > 0; o >>= 1) {
        if (tid < o) { br[tid] += br[tid + o]; bc[tid] += bc[tid + o]; }
        __syncthreads();
    }
    if (tid == 0) {
        out[OFF_R + tn] = br[0];
        out[OFF_C + tn] = bc[0] + cb[0];
    }
}

// ---------------- launch ----------------------------------------------------
extern "C" void kernel_launch(void* const* d_in, const int* in_sizes, int n_in,
                              void* d_out, int out_size) {
    const float* x    = (const float*)d_in[0];
    const float* a    = (const float*)d_in[1];
    const float* h0   = (const float*)d_in[2];
    const float* encW = (const float*)d_in[3];
    const float* encb = (const float*)d_in[4];
    const float* Wih  = (const float*)d_in[5];
    const float* Whh  = (const float*)d_in[6];
    const float* bih  = (const float*)d_in[7];
    const float* bhh  = (const float*)d_in[8];
    const float* decW = (const float*)d_in[9];
    const float* decb = (const float*)d_in[10];
    const float* dynW = (const float*)d_in[11];
    const float* dynb = (const float*)d_in[12];
    const float* rewW = (const float*)d_in[13];
    const float* conW = (const float*)d_in[14];
    const float* conb = (const float*)d_in[15];
    float* out = (float*)d_out;

    float *p_ee, *p_ai, *p_h, *p_Wcat, *p_WihT;
    cudaGetSymbolAddress((void**)&p_ee,   g_ee);
    cudaGetSymbolAddress((void**)&p_ai,   g_ai);
    cudaGetSymbolAddress((void**)&p_h,    g_h);
    cudaGetSymbolAddress((void**)&p_Wcat, g_Wcat);
    cudaGetSymbolAddress((void**)&p_WihT, g_WihT);

    // --- parallel precompute ---
    // Launch order keeps sgemm_ee at slot #4 (the profiled launch).
    keys_k<<<1, 64>>>();                                                     // 1
    gumbel_k<<<(int)(((size_t)TNP * ZDIM + 255) / 256), 256>>>();            // 2
    transpose_k<<<dim3(32, 96), dim3(32, 8)>>>(Whh, p_Wcat, G3, HD, NCAT);   // 3
    // ee = e @ enc_W[H:] + enc_b   [16384,1024]x[1024,1024]  (BK=16, dbuf)
    sgemm_k<128,128,16,8,8><<<dim3(ZDIM / 128, TNP / 128), 256>>>(           // 4 (profiled)
        x, ZDIM, encW + (size_t)HD * ZDIM, ZDIM, p_ee, ZDIM, ZDIM, encb);
    enccopy_k<<<4096, 256>>>(encW);                                          // 5
    transpose_k<<<dim3(34, 96), dim3(32, 8)>>>(Wih, p_WihT, G3, KAW, G3);    // 6
    // ai = a @ Wih_a^T + bih   [16384,48]x[48,3072]  (K=48 -> BK=16)
    sgemm_k<128,128,16,8,8><<<dim3(G3 / 128, TNP / 128), 256>>>(             // 7
        a, AD, p_WihT + (size_t)ZDIM * G3, G3, p_ai, G3, AD, bih);

    // --- sequential rollout ---
    cudaMemcpyAsync(p_h, h0, (size_t)NH * sizeof(float), cudaMemcpyDeviceToDevice, 0);
    for (int t = 0; t < TT; t++) {
        catgemm_k<<<dim3(NCAT / 64, NB / 64), 128>>>(
            p_h + (size_t)t * NH, bhh, p_ee + (size_t)t * NZ,
            out + OFF_PRIOR + (size_t)t * NZ);
        samgru_k<<<NB, 256>>>(t, out + OFF_PRIOR + (size_t)t * NZ, (t < TT - 1) ? 1 : 0);
    }

    // --- parallel heads ---
    sgemm_k<128,128,16,8,8><<<dim3(ZDIM / 128, TNP / 128), 256>>>(
        p_h, HD, decW, ZDIM, out + OFF_X, ZDIM, HD, decb);
    decz_k<<<TNP, 256>>>(decW, out + OFF_X);
    sgemm_k<128,128,16,8,8><<<dim3(ZDIM / 128, TNP / 128), 256>>>(
        p_h, HD, dynW, ZDIM, out + OFF_POST, ZDIM, HD, dynb);
    rc_k<<<TNP, 128>>>(rewW, conW, conb, out);
}